// round 5
// baseline (speedup 1.0000x reference)
#include <cuda_runtime.h>
#include <cuda_bf16.h>
#include <cstdint>
#include <type_traits>

#define BB      8
#define LL      2048
#define DIMM    768
#define DIN     1536
#define DSTATE  16
#define DTRANK  48
#define NROWS   (BB * LL)              // 16384
#define XPROJ   (DTRANK + 2 * DSTATE)  // 80

// ---------------- scratch (static device globals; no allocation allowed) ---
__device__ float g_xz  [(size_t)NROWS * 2 * DIN];
__device__ float g_xc  [(size_t)NROWS * DIN];
__device__ float g_xdbl[(size_t)NROWS * XPROJ];
__device__ float g_dt  [(size_t)NROWS * DIN];

// bf16 hi/lo split operands (plain row-major)
__device__ __align__(128) __nv_bfloat16 g_axh[(size_t)NROWS * DIMM];
__device__ __align__(128) __nv_bfloat16 g_axl[(size_t)NROWS * DIMM];
__device__ __align__(128) __nv_bfloat16 g_wih[(size_t)(2*DIN) * DIMM];
__device__ __align__(128) __nv_bfloat16 g_wil[(size_t)(2*DIN) * DIMM];
__device__ __align__(128) __nv_bfloat16 g_ayh[(size_t)NROWS * DIN];
__device__ __align__(128) __nv_bfloat16 g_ayl[(size_t)NROWS * DIN];
__device__ __align__(128) __nv_bfloat16 g_woh[(size_t)DIMM * DIN];
__device__ __align__(128) __nv_bfloat16 g_wol[(size_t)DIMM * DIN];

// ======================== PTX helpers ============================
__device__ __forceinline__ uint32_t smem_u32(const void* p) {
    uint32_t a;
    asm("{ .reg .u64 t; cvta.to.shared.u64 t, %1; cvt.u32.u64 %0, t; }"
        : "=r"(a) : "l"(p));
    return a;
}
__device__ __forceinline__ void cp16(uint32_t dst, const void* src) {
    asm volatile("cp.async.cg.shared.global [%0], [%1], 16;" :: "r"(dst), "l"(src));
}
__device__ __forceinline__ void cp_commit() {
    asm volatile("cp.async.commit_group;" ::: "memory");
}
#define CP_WAIT(n) asm volatile("cp.async.wait_group %0;" :: "n"(n) : "memory")

#define LDSM4(r0, r1, r2, r3, addr) \
    asm volatile("ldmatrix.sync.aligned.m8n8.x4.shared.b16 {%0,%1,%2,%3}, [%4];" \
                 : "=r"(r0), "=r"(r1), "=r"(r2), "=r"(r3) : "r"(addr))
#define MMA16816(d, a, b) \
    asm volatile("mma.sync.aligned.m16n8k16.row.col.f32.bf16.bf16.f32 " \
                 "{%0,%1,%2,%3},{%4,%5,%6,%7},{%8,%9},{%0,%1,%2,%3};" \
                 : "+f"((d)[0]), "+f"((d)[1]), "+f"((d)[2]), "+f"((d)[3]) \
                 : "r"((a)[0]), "r"((a)[1]), "r"((a)[2]), "r"((a)[3]), \
                   "r"((b)[0]), "r"((b)[1]))

__device__ __forceinline__ void split_bf16(float f, __nv_bfloat16& h, __nv_bfloat16& l) {
    h = __float2bfloat16(f);
    l = __float2bfloat16(f - __bfloat162float(h));
}

// =========================== pack / split kernel (weights) =================
__global__ void pack_split(const float* __restrict__ in,
                           uint4* __restrict__ hi, uint4* __restrict__ lo,
                           long long total8)
{
    const long long idx = (long long)blockIdx.x * blockDim.x + threadIdx.x;
    if (idx >= total8) return;
    const float* p = in + idx * 8;
    uint32_t uh[4], ul[4];
#pragma unroll
    for (int j = 0; j < 4; j++) {
        __nv_bfloat16 h0, h1, l0, l1;
        split_bf16(p[2*j],     h0, l0);
        split_bf16(p[2*j + 1], h1, l1);
        uh[j] = (uint32_t)__bfloat16_as_ushort(h0) | ((uint32_t)__bfloat16_as_ushort(h1) << 16);
        ul[j] = (uint32_t)__bfloat16_as_ushort(l0) | ((uint32_t)__bfloat16_as_ushort(l1) << 16);
    }
    hi[idx] = make_uint4(uh[0], uh[1], uh[2], uh[3]);
    lo[idx] = make_uint4(ul[0], ul[1], ul[2], ul[3]);
}

// ================== mma.sync bf16 3-pass split TN GEMM =====================
// CTA tile 128x128, BK=32, 4-stage cp.async pipe, 8 warps (64x32 warp tiles).
// EPI 0: raw store.  EPI 2: C = mask[m] * (X[m,n] + acc).
#define MM_STG_ROW   40                 // padded row stride in bf16 (80B)
#define MM_BUF       (128 * 80)         // one operand buffer: 10240 B
#define MM_STAGE     (4 * MM_BUF)       // Ah, Al, Bh, Bl: 40960 B
#define MM_NSTG      4
#define MM_SMEM      (MM_NSTG * MM_STAGE)   // 163840 B

template<int EPI>
__global__ __launch_bounds__(256, 1)
void tgemm(const __nv_bfloat16* __restrict__ Ah, const __nv_bfloat16* __restrict__ Al,
           const __nv_bfloat16* __restrict__ Bh, const __nv_bfloat16* __restrict__ Bl,
           float* __restrict__ C, int ldc, int K,
           const float* __restrict__ X, const int* __restrict__ mask)
{
    extern __shared__ char smem[];
    const uint32_t sBase = smem_u32(smem);

    const int tid  = threadIdx.x;
    const int wid  = tid >> 5;
    const int lane = tid & 31;
    const int wm   = wid & 1;          // 2 warps along M (64 each)
    const int wn   = wid >> 1;         // 4 warps along N (32 each)
    const int m0   = blockIdx.y * 128;
    const int n0   = blockIdx.x * 128;
    const int NK   = K / 32;

    auto load_stage = [&](int c) {
        const uint32_t sb = sBase + (c & (MM_NSTG - 1)) * MM_STAGE;
        const int k0 = c * 32;
#pragma unroll
        for (int h = 0; h < 2; h++) {
            const int ch  = tid + h * 256;      // 0..511
            const int row = ch >> 2;
            const int kc  = ch & 3;
            const uint32_t doff = row * 80 + kc * 16;
            const size_t goffA = (size_t)(m0 + row) * K + k0 + kc * 8;
            const size_t goffB = (size_t)(n0 + row) * K + k0 + kc * 8;
            cp16(sb + doff,               Ah + goffA);
            cp16(sb + MM_BUF + doff,      Al + goffA);
            cp16(sb + 2*MM_BUF + doff,    Bh + goffB);
            cp16(sb + 3*MM_BUF + doff,    Bl + goffB);
        }
    };

    float acc[4][4][4];
#pragma unroll
    for (int i = 0; i < 4; i++)
#pragma unroll
        for (int j = 0; j < 4; j++)
#pragma unroll
            for (int r = 0; r < 4; r++) acc[i][j][r] = 0.f;

    load_stage(0); cp_commit();
    load_stage(1); cp_commit();
    load_stage(2); cp_commit();

    // fragment address components (bf16-element units within a buffer)
    const int aRow = wm * 64 + ((lane >> 3) & 1) * 8 + (lane & 7);   // + mi*16
    const int aK   = (lane >> 4) * 8;                                 // + kk*16
    const int bRow = wn * 32 + ((lane >> 4) & 1) * 8 + (lane & 7);    // + nj*16
    const int bK   = ((lane >> 3) & 1) * 8;                           // + kk*16

    for (int c = 0; c < NK; c++) {
        CP_WAIT(2);
        __syncthreads();
        if (c + 3 < NK) load_stage(c + 3);
        cp_commit();
        const uint32_t sb = sBase + (c & (MM_NSTG - 1)) * MM_STAGE;

#pragma unroll
        for (int kk = 0; kk < 2; kk++) {
            uint32_t ah[4][4], al[4][4], bh[4][2], bl[4][2];
#pragma unroll
            for (int mi = 0; mi < 4; mi++) {
                const uint32_t ad = sb + ((aRow + mi * 16) * MM_STG_ROW
                                          + aK + kk * 16) * 2;
                LDSM4(ah[mi][0], ah[mi][1], ah[mi][2], ah[mi][3], ad);
                LDSM4(al[mi][0], al[mi][1], al[mi][2], al[mi][3], ad + MM_BUF);
            }
#pragma unroll
            for (int nj = 0; nj < 2; nj++) {
                const uint32_t bd = sb + 2*MM_BUF + ((bRow + nj * 16) * MM_STG_ROW
                                                     + bK + kk * 16) * 2;
                LDSM4(bh[2*nj][0], bh[2*nj][1], bh[2*nj+1][0], bh[2*nj+1][1], bd);
                LDSM4(bl[2*nj][0], bl[2*nj][1], bl[2*nj+1][0], bl[2*nj+1][1], bd + MM_BUF);
            }
#pragma unroll
            for (int mi = 0; mi < 4; mi++)
#pragma unroll
                for (int ni = 0; ni < 4; ni++) {
                    MMA16816(acc[mi][ni], ah[mi], bh[ni]);
                    MMA16816(acc[mi][ni], ah[mi], bl[ni]);
                    MMA16816(acc[mi][ni], al[mi], bh[ni]);
                }
        }
    }

    // ------------------------------- epilogue -------------------------------
    const int rq = lane >> 2;
    const int cq = (lane & 3) * 2;
#pragma unroll
    for (int mi = 0; mi < 4; mi++) {
        const int r0 = m0 + wm * 64 + mi * 16 + rq;
        const int r1 = r0 + 8;
        float mf0 = 1.f, mf1 = 1.f;
        if (EPI == 2) { mf0 = (float)mask[r0]; mf1 = (float)mask[r1]; }
#pragma unroll
        for (int ni = 0; ni < 4; ni++) {
            const int cc = n0 + wn * 32 + ni * 8 + cq;
            float v0 = acc[mi][ni][0], v1 = acc[mi][ni][1];
            float v2 = acc[mi][ni][2], v3 = acc[mi][ni][3];
            if (EPI == 2) {
                const float* x0 = X + (size_t)r0 * ldc + cc;
                const float* x1 = X + (size_t)r1 * ldc + cc;
                v0 = mf0 * (x0[0] + v0); v1 = mf0 * (x0[1] + v1);
                v2 = mf1 * (x1[0] + v2); v3 = mf1 * (x1[1] + v3);
            }
            *(float2*)(C + (size_t)r0 * ldc + cc) = make_float2(v0, v1);
            *(float2*)(C + (size_t)r1 * ldc + cc) = make_float2(v2, v3);
        }
    }
}

// --------------------------- LayerNorm + fused bf16 split pack -------------
__global__ void ln_kernel(const float* __restrict__ x,
                          const int*   __restrict__ mask,
                          const float* __restrict__ g,
                          const float* __restrict__ b,
                          __nv_bfloat16* __restrict__ xh,
                          __nv_bfloat16* __restrict__ xl)
{
    const int row = blockIdx.x;
    const int t   = threadIdx.x;
    const float* xr = x + (size_t)row * DIMM;

    float v[3];
    float s = 0.f, s2 = 0.f;
#pragma unroll
    for (int j = 0; j < 3; j++) {
        v[j] = xr[t + j * 256];
        s  += v[j];
        s2 += v[j] * v[j];
    }
    __shared__ float red[2][8];
#pragma unroll
    for (int o = 16; o > 0; o >>= 1) {
        s  += __shfl_xor_sync(0xffffffffu, s,  o);
        s2 += __shfl_xor_sync(0xffffffffu, s2, o);
    }
    if ((t & 31) == 0) { red[0][t >> 5] = s; red[1][t >> 5] = s2; }
    __syncthreads();
    float ts = 0.f, ts2 = 0.f;
#pragma unroll
    for (int j = 0; j < 8; j++) { ts += red[0][j]; ts2 += red[1][j]; }

    const float mu   = ts * (1.0f / DIMM);
    const float var  = ts2 * (1.0f / DIMM) - mu * mu;
    const float rstd = rsqrtf(var + 1e-5f);
    const float mf   = (float)mask[row];

#pragma unroll
    for (int j = 0; j < 3; j++) {
        const int c = t + j * 256;
        const float o = ((v[j] - mu) * rstd * g[c] + b[c]) * mf;
        __nv_bfloat16 h, l;
        split_bf16(o, h, l);
        xh[(size_t)row * DIMM + c] = h;
        xl[(size_t)row * DIMM + c] = l;
    }
}

// ------------------------------------------------------- generic TN SGEMM
template<int EPI>
__global__ __launch_bounds__(256, 2)
void gemm_tn(const float* __restrict__ A, int lda,
             const float* __restrict__ Bw, int ldb,
             float* __restrict__ C, int ldc,
             int N, int K,
             const float* __restrict__ bias)
{
    __shared__ float As[16][132];
    __shared__ float Bs[16][132];

    const int tid = threadIdx.x;
    const int m0  = blockIdx.x * 128;
    const int n0  = blockIdx.y * 128;
    const int tx  = (tid & 15) * 8;
    const int ty  = (tid >> 4) * 8;
    const int lr  = tid >> 2;
    const int lc  = (tid & 3) * 4;

    float acc[8][8];
#pragma unroll
    for (int i = 0; i < 8; i++)
#pragma unroll
        for (int j = 0; j < 8; j++) acc[i][j] = 0.f;

    for (int k0 = 0; k0 < K; k0 += 16) {
#pragma unroll
        for (int h = 0; h < 2; h++) {
            const int r = lr + h * 64;
            float4 v = *(const float4*)(A + (size_t)(m0 + r) * lda + (k0 + lc));
            As[lc + 0][r] = v.x; As[lc + 1][r] = v.y;
            As[lc + 2][r] = v.z; As[lc + 3][r] = v.w;
            float4 w = make_float4(0.f, 0.f, 0.f, 0.f);
            if (n0 + r < N)
                w = *(const float4*)(Bw + (size_t)(n0 + r) * ldb + (k0 + lc));
            Bs[lc + 0][r] = w.x; Bs[lc + 1][r] = w.y;
            Bs[lc + 2][r] = w.z; Bs[lc + 3][r] = w.w;
        }
        __syncthreads();
#pragma unroll
        for (int k = 0; k < 16; k++) {
            float a[8], bb[8];
            *(float4*)(a)      = *(const float4*)&As[k][ty];
            *(float4*)(a + 4)  = *(const float4*)&As[k][ty + 4];
            *(float4*)(bb)     = *(const float4*)&Bs[k][tx];
            *(float4*)(bb + 4) = *(const float4*)&Bs[k][tx + 4];
#pragma unroll
            for (int i = 0; i < 8; i++)
#pragma unroll
                for (int j = 0; j < 8; j++)
                    acc[i][j] = fmaf(a[i], bb[j], acc[i][j]);
        }
        __syncthreads();
    }

#pragma unroll
    for (int i = 0; i < 8; i++) {
        const int r = m0 + ty + i;
#pragma unroll
        for (int j = 0; j < 8; j++) {
            const int c = n0 + tx + j;
            if (c < N) {
                float v = acc[i][j];
                if (EPI == 1) {
                    v += bias[c];
                    v = (v > 20.f) ? v : log1pf(__expf(v));
                }
                C[(size_t)r * ldc + c] = v;
            }
        }
    }
}

// ------------------------------------------- depthwise causal conv4 + SiLU
__global__ void conv_silu(const float* __restrict__ xz,
                          const float* __restrict__ w,
                          const float* __restrict__ bias,
                          float* __restrict__ xc)
{
    const long long idx4 = (long long)blockIdx.x * blockDim.x + threadIdx.x;
    if (idx4 >= (long long)NROWS * DIN / 4) return;
    const int d = (int)((idx4 * 4) % DIN);
    const long long i = (idx4 * 4) / DIN;
    const int l = (int)(i % LL);

    float4 s = *(const float4*)(bias + d);
    const float4 w0 = *(const float4*)(w + (d + 0) * 4);   // taps of channel d
    const float4 w1 = *(const float4*)(w + (d + 1) * 4);
    const float4 w2 = *(const float4*)(w + (d + 2) * 4);
    const float4 w3 = *(const float4*)(w + (d + 3) * 4);
#pragma unroll
    for (int j = 0; j < 4; j++) {
        if (l - 3 + j >= 0) {
            const float4 v = *(const float4*)(xz + (size_t)(i - 3 + j) * (2 * DIN) + d);
            s.x = fmaf((&w0.x)[j], v.x, s.x);
            s.y = fmaf((&w1.x)[j], v.y, s.y);
            s.z = fmaf((&w2.x)[j], v.z, s.z);
            s.w = fmaf((&w3.x)[j], v.w, s.w);
        }
    }
    float4 o;
    o.x = s.x / (1.f + __expf(-s.x));
    o.y = s.y / (1.f + __expf(-s.y));
    o.z = s.z / (1.f + __expf(-s.z));
    o.w = s.w / (1.f + __expf(-s.w));
    *(float4*)(xc + idx4 * 4) = o;
}

// ------------------------------------------------------------ selective scan
// One thread per (batch, channel). SSTAGE=16 deep cp.async pipe, 2 steps/iter.
// Writes gated output directly as bf16 hi/lo split (feeds out_proj tensor GEMM).
#define SSTAGE 16
#define STAGEF 416   // 128 dt + 128 xc + 128 z + 32 bc

__global__ __launch_bounds__(128)
void scan_kernel(const float* __restrict__ dt,
                 const float* __restrict__ xc,
                 const float* __restrict__ xz,
                 const float* __restrict__ xdbl,
                 const float* __restrict__ A_log,
                 const float* __restrict__ Dp,
                 __nv_bfloat16* __restrict__ yh,
                 __nv_bfloat16* __restrict__ yl)
{
    __shared__ float sbuf[SSTAGE][STAGEF];

    const int b     = blockIdx.x / (DIN / 128);
    const int chunk = blockIdx.x % (DIN / 128);
    const int t     = threadIdx.x;
    const int d     = chunk * 128 + t;
    const size_t rowbase = (size_t)b * LL;

    float a[DSTATE];
#pragma unroll
    for (int s = 0; s < DSTATE; s++) a[s] = -__expf(A_log[d * DSTATE + s]);

    bool fast = true;
#pragma unroll
    for (int s = 1; s < DSTATE; s++) {
        const float ideal = a[0] * (float)(s + 1);
        if (fabsf(a[s] - ideal) > 1e-4f * fabsf(ideal)) fast = false;
    }
    fast = __syncthreads_and(fast ? 1 : 0);

    const float LOG2E = 1.44269504088896f;
    const float c1 = a[0] * LOG2E;
    float cs[DSTATE];
#pragma unroll
    for (int s = 0; s < DSTATE; s++) cs[s] = a[s] * LOG2E;
    const float dpv = Dp[d];

    float h[DSTATE];
#pragma unroll
    for (int s = 0; s < DSTATE; s++) h[s] = 0.f;

    const int role = t >> 5;
    const int lane = t & 31;

    auto issue = [&](int tt) {
        const int slot = tt & (SSTAGE - 1);
        const size_t row = rowbase + tt;
        const float* gp = nullptr;
        int soff = 0;
        bool active = true;
        if (role == 0)      { gp = dt + row * DIN + chunk * 128 + lane * 4;                soff = lane * 4; }
        else if (role == 1) { gp = xc + row * DIN + chunk * 128 + lane * 4;                soff = 128 + lane * 4; }
        else if (role == 2) { gp = xz + row * (2 * DIN) + DIN + chunk * 128 + lane * 4;    soff = 256 + lane * 4; }
        else                { active = (lane < 8);
                              gp = xdbl + row * XPROJ + DTRANK + lane * 4;                 soff = 384 + lane * 4; }
        if (active)
            cp16((uint32_t)__cvta_generic_to_shared(&sbuf[slot][soff]), gp);
        cp_commit();
    };

    for (int tt = 0; tt < SSTAGE - 2; tt++) issue(tt);   // 14 stages ahead

    auto run = [&](auto fastc) {
        constexpr bool FAST = decltype(fastc)::value;
        for (int tt = 0; tt < LL; tt += 2) {
            CP_WAIT(SSTAGE - 4);   // oldest 2 stages complete
            __syncthreads();
            if (tt + SSTAGE - 2 < LL) issue(tt + SSTAGE - 2);
            if (tt + SSTAGE - 1 < LL) issue(tt + SSTAGE - 1);

#pragma unroll
            for (int q2 = 0; q2 < 2; q2++) {
                const int step = tt + q2;
                const int slot = step & (SSTAGE - 1);
                const float u  = sbuf[slot][t];
                const float xv = sbuf[slot][128 + t];
                const float zv = sbuf[slot][256 + t];
                float Bv[DSTATE], Cv[DSTATE];
#pragma unroll
                for (int q = 0; q < 4; q++) {
                    float4 vb = *(const float4*)&sbuf[slot][384 + q * 4];
                    float4 vc = *(const float4*)&sbuf[slot][400 + q * 4];
                    Bv[q*4+0] = vb.x; Bv[q*4+1] = vb.y; Bv[q*4+2] = vb.z; Bv[q*4+3] = vb.w;
                    Cv[q*4+0] = vc.x; Cv[q*4+1] = vc.y; Cv[q*4+2] = vc.z; Cv[q*4+3] = vc.w;
                }

                float e[DSTATE];
                if (FAST) {
                    const float r = exp2f(u * c1);
                    e[0]  = r;
                    e[1]  = r * r;
                    e[3]  = e[1] * e[1];
                    e[7]  = e[3] * e[3];
                    e[15] = e[7] * e[7];
                    e[2]  = e[1] * r;
                    e[4]  = e[3] * r;     e[5]  = e[3] * e[1];  e[6]  = e[3] * e[2];
                    e[8]  = e[7] * r;     e[9]  = e[7] * e[1];  e[10] = e[7] * e[2];
                    e[11] = e[7] * e[3];  e[12] = e[7] * e[4];  e[13] = e[7] * e[5];
                    e[14] = e[7] * e[6];
                } else {
#pragma unroll
                    for (int s = 0; s < DSTATE; s++) e[s] = exp2f(u * cs[s]);
                }

                const float ux = u * xv;
                float y0 = 0.f, y1 = 0.f, y2 = 0.f, y3 = 0.f;
#pragma unroll
                for (int s = 0; s < DSTATE; s += 4) {
                    h[s+0] = fmaf(e[s+0], h[s+0], ux * Bv[s+0]);
                    h[s+1] = fmaf(e[s+1], h[s+1], ux * Bv[s+1]);
                    h[s+2] = fmaf(e[s+2], h[s+2], ux * Bv[s+2]);
                    h[s+3] = fmaf(e[s+3], h[s+3], ux * Bv[s+3]);
                    y0 = fmaf(h[s+0], Cv[s+0], y0);
                    y1 = fmaf(h[s+1], Cv[s+1], y1);
                    y2 = fmaf(h[s+2], Cv[s+2], y2);
                    y3 = fmaf(h[s+3], Cv[s+3], y3);
                }
                float yt = (y0 + y1) + (y2 + y3);
                yt = fmaf(xv, dpv, yt);
                const float sig = 1.f / (1.f + __expf(-zv));
                const float out = yt * (zv * sig);
                __nv_bfloat16 oh, ol;
                split_bf16(out, oh, ol);
                const size_t oidx = (rowbase + step) * DIN + chunk * 128 + t;
                yh[oidx] = oh;
                yl[oidx] = ol;
            }
        }
    };

    if (fast) run(std::true_type{});
    else      run(std::false_type{});
}

// ------------------------------------------------------------------- launch
extern "C" void kernel_launch(void* const* d_in, const int* in_sizes, int n_in,
                              void* d_out, int out_size)
{
    const float* x      = (const float*)d_in[0];
    const int*   mask   = (const int*)  d_in[1];
    const float* ln_g   = (const float*)d_in[2];
    const float* ln_b   = (const float*)d_in[3];
    const float* W_in   = (const float*)d_in[4];
    const float* conv_w = (const float*)d_in[5];
    const float* conv_b = (const float*)d_in[6];
    const float* W_xp   = (const float*)d_in[7];
    const float* W_dt   = (const float*)d_in[8];
    const float* b_dt   = (const float*)d_in[9];
    const float* A_log  = (const float*)d_in[10];
    const float* Dp     = (const float*)d_in[11];
    const float* W_out  = (const float*)d_in[12];
    float* out = (float*)d_out;

    static float *p_xz = nullptr, *p_xc, *p_xdbl, *p_dt;
    static __nv_bfloat16 *p_axh, *p_axl, *p_wih, *p_wil, *p_ayh, *p_ayl, *p_woh, *p_wol;
    if (!p_xz) {
        cudaGetSymbolAddress((void**)&p_xz,   g_xz);
        cudaGetSymbolAddress((void**)&p_xc,   g_xc);
        cudaGetSymbolAddress((void**)&p_xdbl, g_xdbl);
        cudaGetSymbolAddress((void**)&p_dt,   g_dt);
        cudaGetSymbolAddress((void**)&p_axh,  g_axh);
        cudaGetSymbolAddress((void**)&p_axl,  g_axl);
        cudaGetSymbolAddress((void**)&p_wih,  g_wih);
        cudaGetSymbolAddress((void**)&p_wil,  g_wil);
        cudaGetSymbolAddress((void**)&p_ayh,  g_ayh);
        cudaGetSymbolAddress((void**)&p_ayl,  g_ayl);
        cudaGetSymbolAddress((void**)&p_woh,  g_woh);
        cudaGetSymbolAddress((void**)&p_wol,  g_wol);
        cudaFuncSetAttribute(tgemm<0>, cudaFuncAttributeMaxDynamicSharedMemorySize, MM_SMEM);
        cudaFuncSetAttribute(tgemm<2>, cudaFuncAttributeMaxDynamicSharedMemorySize, MM_SMEM);
    }

    // 1. LayerNorm + mask + bf16 split pack
    ln_kernel<<<NROWS, 256>>>(x, mask, ln_g, ln_b, p_axh, p_axl);

    // 2. pack weights
    {
        long long nW = (long long)(2 * DIN) * DIMM / 8;
        pack_split<<<(unsigned)((nW + 255) / 256), 256>>>(W_in, (uint4*)p_wih, (uint4*)p_wil, nW);
        long long nO = (long long)DIMM * DIN / 8;
        pack_split<<<(unsigned)((nO + 255) / 256), 256>>>(W_out, (uint4*)p_woh, (uint4*)p_wol, nO);
    }

    // 3. in_proj on tensor pipe: xz = xn @ W_in^T   (16384 x 3072, K=768)
    {
        dim3 g((2 * DIN) / 128, NROWS / 128);
        tgemm<0><<<g, 256, MM_SMEM>>>(p_axh, p_axl, p_wih, p_wil,
                                      p_xz, 2 * DIN, DIMM, nullptr, nullptr);
    }

    // 4. depthwise causal conv + SiLU
    {
        const long long n4 = (long long)NROWS * DIN / 4;
        conv_silu<<<(unsigned)((n4 + 255) / 256), 256>>>(p_xz, conv_w, conv_b, p_xc);
    }

    // 5. x_proj: xdbl = xc @ W_xp^T   (16384 x 80, K=1536)
    {
        dim3 g(NROWS / 128, 1);
        gemm_tn<0><<<g, 256>>>(p_xc, DIN, W_xp, DIN, p_xdbl, XPROJ,
                               XPROJ, DIN, nullptr);
    }

    // 6. dt_proj + softplus
    {
        dim3 g(NROWS / 128, DIN / 128);
        gemm_tn<1><<<g, 256>>>(p_xdbl, XPROJ, W_dt, DTRANK, p_dt, DIN,
                               DIN, DTRANK, b_dt);
    }

    // 7. selective scan + D-skip + SiLU gate -> bf16 hi/lo y
    scan_kernel<<<BB * (DIN / 128), 128>>>(p_dt, p_xc, p_xz, p_xdbl,
                                           A_log, Dp, p_ayh, p_ayl);

    // 8. out_proj on tensor pipe + residual + mask
    {
        dim3 g(DIMM / 128, NROWS / 128);
        tgemm<2><<<g, 256, MM_SMEM>>>(p_ayh, p_ayl, p_woh, p_wol,
                                      out, DIMM, DIN, x, mask);
    }
}

// round 6
// speedup vs baseline: 1.0735x; 1.0735x over previous
#include <cuda_runtime.h>
#include <cuda_bf16.h>
#include <cstdint>
#include <type_traits>

#define BB      8
#define LL      2048
#define DIMM    768
#define DIN     1536
#define DSTATE  16
#define DTRANK  48
#define NROWS   (BB * LL)              // 16384
#define XPROJ   (DTRANK + 2 * DSTATE)  // 80

// ---------------- scratch (static device globals; no allocation allowed) ---
__device__ float g_xz  [(size_t)NROWS * 2 * DIN];
__device__ float g_xc  [(size_t)NROWS * DIN];
__device__ float g_xdbl[(size_t)NROWS * XPROJ];
__device__ float g_dt  [(size_t)NROWS * DIN];

// bf16 hi/lo split operands (plain row-major)
__device__ __align__(128) __nv_bfloat16 g_axh[(size_t)NROWS * DIMM];
__device__ __align__(128) __nv_bfloat16 g_axl[(size_t)NROWS * DIMM];
__device__ __align__(128) __nv_bfloat16 g_wih[(size_t)(2*DIN) * DIMM];
__device__ __align__(128) __nv_bfloat16 g_wil[(size_t)(2*DIN) * DIMM];
__device__ __align__(128) __nv_bfloat16 g_ayh[(size_t)NROWS * DIN];
__device__ __align__(128) __nv_bfloat16 g_ayl[(size_t)NROWS * DIN];
__device__ __align__(128) __nv_bfloat16 g_woh[(size_t)DIMM * DIN];
__device__ __align__(128) __nv_bfloat16 g_wol[(size_t)DIMM * DIN];

// ======================== PTX helpers ============================
__device__ __forceinline__ uint32_t smem_u32(const void* p) {
    uint32_t a;
    asm("{ .reg .u64 t; cvta.to.shared.u64 t, %1; cvt.u32.u64 %0, t; }"
        : "=r"(a) : "l"(p));
    return a;
}
__device__ __forceinline__ void cp16(uint32_t dst, const void* src) {
    asm volatile("cp.async.cg.shared.global [%0], [%1], 16;" :: "r"(dst), "l"(src));
}
__device__ __forceinline__ void cp_commit() {
    asm volatile("cp.async.commit_group;" ::: "memory");
}
#define CP_WAIT(n) asm volatile("cp.async.wait_group %0;" :: "n"(n) : "memory")

#define LDSM4(r0, r1, r2, r3, addr) \
    asm volatile("ldmatrix.sync.aligned.m8n8.x4.shared.b16 {%0,%1,%2,%3}, [%4];" \
                 : "=r"(r0), "=r"(r1), "=r"(r2), "=r"(r3) : "r"(addr))
#define LDSM2(r0, r1, addr) \
    asm volatile("ldmatrix.sync.aligned.m8n8.x2.shared.b16 {%0,%1}, [%2];" \
                 : "=r"(r0), "=r"(r1) : "r"(addr))
#define MMA16816(d, a, b) \
    asm volatile("mma.sync.aligned.m16n8k16.row.col.f32.bf16.bf16.f32 " \
                 "{%0,%1,%2,%3},{%4,%5,%6,%7},{%8,%9},{%0,%1,%2,%3};" \
                 : "+f"((d)[0]), "+f"((d)[1]), "+f"((d)[2]), "+f"((d)[3]) \
                 : "r"((a)[0]), "r"((a)[1]), "r"((a)[2]), "r"((a)[3]), \
                   "r"((b)[0]), "r"((b)[1]))

__device__ __forceinline__ void split_bf16(float f, __nv_bfloat16& h, __nv_bfloat16& l) {
    h = __float2bfloat16(f);
    l = __float2bfloat16(f - __bfloat162float(h));
}

// =========================== pack / split kernel (weights) =================
__global__ void pack_split(const float* __restrict__ in,
                           uint4* __restrict__ hi, uint4* __restrict__ lo,
                           long long total8)
{
    const long long idx = (long long)blockIdx.x * blockDim.x + threadIdx.x;
    if (idx >= total8) return;
    const float* p = in + idx * 8;
    uint32_t uh[4], ul[4];
#pragma unroll
    for (int j = 0; j < 4; j++) {
        __nv_bfloat16 h0, h1, l0, l1;
        split_bf16(p[2*j],     h0, l0);
        split_bf16(p[2*j + 1], h1, l1);
        uh[j] = (uint32_t)__bfloat16_as_ushort(h0) | ((uint32_t)__bfloat16_as_ushort(h1) << 16);
        ul[j] = (uint32_t)__bfloat16_as_ushort(l0) | ((uint32_t)__bfloat16_as_ushort(l1) << 16);
    }
    hi[idx] = make_uint4(uh[0], uh[1], uh[2], uh[3]);
    lo[idx] = make_uint4(ul[0], ul[1], ul[2], ul[3]);
}

// ================== mma.sync bf16 3-pass split TN GEMM =====================
// (round-4 measured-best structure: 3-stage cp.async pipe, CP_WAIT(1),
//  LDSM2 B-fragments, loads issued after compute)
#define MM_STG_ROW   40                 // padded row stride in bf16 elems (80B)
#define MM_BUF       (128 * 80)         // one operand buffer: 10240 B
#define MM_STAGE     (4 * MM_BUF)       // Ah, Al, Bh, Bl: 40960 B
#define MM_SMEM      (3 * MM_STAGE)     // 3 stages: 122880 B

template<int EPI>
__global__ __launch_bounds__(256, 1)
void tgemm(const __nv_bfloat16* __restrict__ Ah, const __nv_bfloat16* __restrict__ Al,
           const __nv_bfloat16* __restrict__ Bh, const __nv_bfloat16* __restrict__ Bl,
           float* __restrict__ C, int ldc, int K,
           const float* __restrict__ X, const int* __restrict__ mask)
{
    extern __shared__ char smem[];
    const uint32_t sBase = smem_u32(smem);

    const int tid  = threadIdx.x;
    const int wid  = tid >> 5;
    const int lane = tid & 31;
    const int wm   = wid & 1;          // 2 warps along M (64 each)
    const int wn   = wid >> 1;         // 4 warps along N (32 each)
    const int m0   = blockIdx.y * 128;
    const int n0   = blockIdx.x * 128;
    const int NK   = K / 32;

    auto load_stage = [&](int c, int slot) {
        const uint32_t sb = sBase + slot * MM_STAGE;
        const int k0 = c * 32;
#pragma unroll
        for (int h = 0; h < 2; h++) {
            const int ch  = tid + h * 256;      // 0..511
            const int row = ch >> 2;
            const int kc  = ch & 3;
            const uint32_t doff = row * 80 + kc * 16;
            const size_t goffA = (size_t)(m0 + row) * K + k0 + kc * 8;
            const size_t goffB = (size_t)(n0 + row) * K + k0 + kc * 8;
            cp16(sb + doff,               Ah + goffA);
            cp16(sb + MM_BUF + doff,      Al + goffA);
            cp16(sb + 2*MM_BUF + doff,    Bh + goffB);
            cp16(sb + 3*MM_BUF + doff,    Bl + goffB);
        }
    };

    float acc[4][4][4];
#pragma unroll
    for (int i = 0; i < 4; i++)
#pragma unroll
        for (int j = 0; j < 4; j++)
#pragma unroll
            for (int r = 0; r < 4; r++) acc[i][j][r] = 0.f;

    load_stage(0, 0); cp_commit();
    load_stage(1, 1); cp_commit();

    // fragment address offsets (within a buffer), bf16-element units
    const int aRowB = wm * 64 + ((lane >> 3) & 1) * 8 + (lane & 7);  // + mi*16
    const int aKB   = (lane >> 4) * 8;                               // + kk*16
    const int bRowB = wn * 32 + (lane & 7);                          // + ni*8
    const int bKB   = ((lane >> 3) & 1) * 8;                         // + kk*16

    for (int c = 0; c < NK; c++) {
        CP_WAIT(1);
        __syncthreads();
        const uint32_t sb = sBase + (c % 3) * MM_STAGE;

#pragma unroll
        for (int kk = 0; kk < 2; kk++) {
            uint32_t ah[4][4], al[4][4], bh[4][2], bl[4][2];
#pragma unroll
            for (int mi = 0; mi < 4; mi++) {
                const uint32_t ad = sb + ((aRowB + mi * 16) * MM_STG_ROW
                                          + aKB + kk * 16) * 2;
                LDSM4(ah[mi][0], ah[mi][1], ah[mi][2], ah[mi][3], ad);
                LDSM4(al[mi][0], al[mi][1], al[mi][2], al[mi][3], ad + MM_BUF);
            }
#pragma unroll
            for (int ni = 0; ni < 4; ni++) {
                const uint32_t bd = sb + 2*MM_BUF + ((bRowB + ni * 8) * MM_STG_ROW
                                                     + bKB + kk * 16) * 2;
                LDSM2(bh[ni][0], bh[ni][1], bd);
                LDSM2(bl[ni][0], bl[ni][1], bd + MM_BUF);
            }
#pragma unroll
            for (int mi = 0; mi < 4; mi++)
#pragma unroll
                for (int ni = 0; ni < 4; ni++) {
                    MMA16816(acc[mi][ni], ah[mi], bh[ni]);
                    MMA16816(acc[mi][ni], ah[mi], bl[ni]);
                    MMA16816(acc[mi][ni], al[mi], bh[ni]);
                }
        }

        if (c + 2 < NK) load_stage(c + 2, (c + 2) % 3);
        cp_commit();
    }

    // ------------------------------- epilogue -------------------------------
    const int rq = lane >> 2;
    const int cq = (lane & 3) * 2;
#pragma unroll
    for (int mi = 0; mi < 4; mi++) {
        const int r0 = m0 + wm * 64 + mi * 16 + rq;
        const int r1 = r0 + 8;
        float mf0 = 1.f, mf1 = 1.f;
        if (EPI == 2) { mf0 = (float)mask[r0]; mf1 = (float)mask[r1]; }
#pragma unroll
        for (int ni = 0; ni < 4; ni++) {
            const int cc = n0 + wn * 32 + ni * 8 + cq;
            float v0 = acc[mi][ni][0], v1 = acc[mi][ni][1];
            float v2 = acc[mi][ni][2], v3 = acc[mi][ni][3];
            if (EPI == 2) {
                const float* x0 = X + (size_t)r0 * ldc + cc;
                const float* x1 = X + (size_t)r1 * ldc + cc;
                v0 = mf0 * (x0[0] + v0); v1 = mf0 * (x0[1] + v1);
                v2 = mf1 * (x1[0] + v2); v3 = mf1 * (x1[1] + v3);
            }
            *(float2*)(C + (size_t)r0 * ldc + cc) = make_float2(v0, v1);
            *(float2*)(C + (size_t)r1 * ldc + cc) = make_float2(v2, v3);
        }
    }
}

// --------------------------- LayerNorm + fused bf16 split pack -------------
__global__ void ln_kernel(const float* __restrict__ x,
                          const int*   __restrict__ mask,
                          const float* __restrict__ g,
                          const float* __restrict__ b,
                          __nv_bfloat16* __restrict__ xh,
                          __nv_bfloat16* __restrict__ xl)
{
    const int row = blockIdx.x;
    const int t   = threadIdx.x;
    const float* xr = x + (size_t)row * DIMM;

    float v[3];
    float s = 0.f, s2 = 0.f;
#pragma unroll
    for (int j = 0; j < 3; j++) {
        v[j] = xr[t + j * 256];
        s  += v[j];
        s2 += v[j] * v[j];
    }
    __shared__ float red[2][8];
#pragma unroll
    for (int o = 16; o > 0; o >>= 1) {
        s  += __shfl_xor_sync(0xffffffffu, s,  o);
        s2 += __shfl_xor_sync(0xffffffffu, s2, o);
    }
    if ((t & 31) == 0) { red[0][t >> 5] = s; red[1][t >> 5] = s2; }
    __syncthreads();
    float ts = 0.f, ts2 = 0.f;
#pragma unroll
    for (int j = 0; j < 8; j++) { ts += red[0][j]; ts2 += red[1][j]; }

    const float mu   = ts * (1.0f / DIMM);
    const float var  = ts2 * (1.0f / DIMM) - mu * mu;
    const float rstd = rsqrtf(var + 1e-5f);
    const float mf   = (float)mask[row];

#pragma unroll
    for (int j = 0; j < 3; j++) {
        const int c = t + j * 256;
        const float o = ((v[j] - mu) * rstd * g[c] + b[c]) * mf;
        __nv_bfloat16 h, l;
        split_bf16(o, h, l);
        xh[(size_t)row * DIMM + c] = h;
        xl[(size_t)row * DIMM + c] = l;
    }
}

// ------------------------------------------------------- generic TN SGEMM
template<int EPI>
__global__ __launch_bounds__(256, 2)
void gemm_tn(const float* __restrict__ A, int lda,
             const float* __restrict__ Bw, int ldb,
             float* __restrict__ C, int ldc,
             int N, int K,
             const float* __restrict__ bias)
{
    __shared__ float As[16][132];
    __shared__ float Bs[16][132];

    const int tid = threadIdx.x;
    const int m0  = blockIdx.x * 128;
    const int n0  = blockIdx.y * 128;
    const int tx  = (tid & 15) * 8;
    const int ty  = (tid >> 4) * 8;
    const int lr  = tid >> 2;
    const int lc  = (tid & 3) * 4;

    float acc[8][8];
#pragma unroll
    for (int i = 0; i < 8; i++)
#pragma unroll
        for (int j = 0; j < 8; j++) acc[i][j] = 0.f;

    for (int k0 = 0; k0 < K; k0 += 16) {
#pragma unroll
        for (int h = 0; h < 2; h++) {
            const int r = lr + h * 64;
            float4 v = *(const float4*)(A + (size_t)(m0 + r) * lda + (k0 + lc));
            As[lc + 0][r] = v.x; As[lc + 1][r] = v.y;
            As[lc + 2][r] = v.z; As[lc + 3][r] = v.w;
            float4 w = make_float4(0.f, 0.f, 0.f, 0.f);
            if (n0 + r < N)
                w = *(const float4*)(Bw + (size_t)(n0 + r) * ldb + (k0 + lc));
            Bs[lc + 0][r] = w.x; Bs[lc + 1][r] = w.y;
            Bs[lc + 2][r] = w.z; Bs[lc + 3][r] = w.w;
        }
        __syncthreads();
#pragma unroll
        for (int k = 0; k < 16; k++) {
            float a[8], bb[8];
            *(float4*)(a)      = *(const float4*)&As[k][ty];
            *(float4*)(a + 4)  = *(const float4*)&As[k][ty + 4];
            *(float4*)(bb)     = *(const float4*)&Bs[k][tx];
            *(float4*)(bb + 4) = *(const float4*)&Bs[k][tx + 4];
#pragma unroll
            for (int i = 0; i < 8; i++)
#pragma unroll
                for (int j = 0; j < 8; j++)
                    acc[i][j] = fmaf(a[i], bb[j], acc[i][j]);
        }
        __syncthreads();
    }

#pragma unroll
    for (int i = 0; i < 8; i++) {
        const int r = m0 + ty + i;
#pragma unroll
        for (int j = 0; j < 8; j++) {
            const int c = n0 + tx + j;
            if (c < N) {
                float v = acc[i][j];
                if (EPI == 1) {
                    v += bias[c];
                    v = (v > 20.f) ? v : log1pf(__expf(v));
                }
                C[(size_t)r * ldc + c] = v;
            }
        }
    }
}

// ------------------------------------------- depthwise causal conv4 + SiLU
__global__ void conv_silu(const float* __restrict__ xz,
                          const float* __restrict__ w,
                          const float* __restrict__ bias,
                          float* __restrict__ xc)
{
    const long long idx = (long long)blockIdx.x * blockDim.x + threadIdx.x;
    if (idx >= (long long)NROWS * DIN) return;
    const int d = (int)(idx % DIN);
    const int i = (int)(idx / DIN);
    const int l = i % LL;

    float s = bias[d];
    const float* wp = w + d * 4;
#pragma unroll
    for (int j = 0; j < 4; j++) {
        const int ll = l - 3 + j;
        if (ll >= 0)
            s = fmaf(wp[j], xz[(size_t)(i - 3 + j) * (2 * DIN) + d], s);
    }
    const float sig = 1.f / (1.f + __expf(-s));
    xc[idx] = s * sig;
}

// ------------------------------------------------------------ selective scan
// (round-4 measured-best structure: SSTAGE=8, 1 step/iter, CP_WAIT(6))
// Output fused to bf16 hi/lo split (feeds out_proj tensor GEMM directly).
#define SSTAGE 8
#define STAGEF 416   // 128 dt + 128 xc + 128 z + 32 bc

__global__ __launch_bounds__(128)
void scan_kernel(const float* __restrict__ dt,
                 const float* __restrict__ xc,
                 const float* __restrict__ xz,
                 const float* __restrict__ xdbl,
                 const float* __restrict__ A_log,
                 const float* __restrict__ Dp,
                 __nv_bfloat16* __restrict__ yh,
                 __nv_bfloat16* __restrict__ yl)
{
    __shared__ float sbuf[SSTAGE][STAGEF];

    const int b     = blockIdx.x / (DIN / 128);
    const int chunk = blockIdx.x % (DIN / 128);
    const int t     = threadIdx.x;
    const int d     = chunk * 128 + t;
    const size_t rowbase = (size_t)b * LL;

    float a[DSTATE];
#pragma unroll
    for (int s = 0; s < DSTATE; s++) a[s] = -__expf(A_log[d * DSTATE + s]);

    bool fast = true;
#pragma unroll
    for (int s = 1; s < DSTATE; s++) {
        const float ideal = a[0] * (float)(s + 1);
        if (fabsf(a[s] - ideal) > 1e-4f * fabsf(ideal)) fast = false;
    }
    fast = __syncthreads_and(fast ? 1 : 0);

    const float LOG2E = 1.44269504088896f;
    const float c1 = a[0] * LOG2E;
    float cs[DSTATE];
#pragma unroll
    for (int s = 0; s < DSTATE; s++) cs[s] = a[s] * LOG2E;
    const float dpv = Dp[d];

    float h[DSTATE];
#pragma unroll
    for (int s = 0; s < DSTATE; s++) h[s] = 0.f;

    const int role = t >> 5;
    const int lane = t & 31;

    auto issue = [&](int tt) {
        const int slot = tt & (SSTAGE - 1);
        const size_t row = rowbase + tt;
        const float* gp = nullptr;
        int soff = 0;
        bool active = true;
        if (role == 0)      { gp = dt + row * DIN + chunk * 128 + lane * 4;                soff = lane * 4; }
        else if (role == 1) { gp = xc + row * DIN + chunk * 128 + lane * 4;                soff = 128 + lane * 4; }
        else if (role == 2) { gp = xz + row * (2 * DIN) + DIN + chunk * 128 + lane * 4;    soff = 256 + lane * 4; }
        else                { active = (lane < 8);
                              gp = xdbl + row * XPROJ + DTRANK + lane * 4;                 soff = 384 + lane * 4; }
        if (active)
            cp16((uint32_t)__cvta_generic_to_shared(&sbuf[slot][soff]), gp);
        cp_commit();
    };

    for (int tt = 0; tt < SSTAGE - 1; tt++) issue(tt);

    auto run = [&](auto fastc) {
        constexpr bool FAST = decltype(fastc)::value;
        for (int tt = 0; tt < LL; tt++) {
            CP_WAIT(SSTAGE - 2);
            __syncthreads();
            if (tt + SSTAGE - 1 < LL) issue(tt + SSTAGE - 1);

            const int slot = tt & (SSTAGE - 1);
            const float u  = sbuf[slot][t];
            const float xv = sbuf[slot][128 + t];
            const float zv = sbuf[slot][256 + t];
            float Bv[DSTATE], Cv[DSTATE];
#pragma unroll
            for (int q = 0; q < 4; q++) {
                float4 vb = *(const float4*)&sbuf[slot][384 + q * 4];
                float4 vc = *(const float4*)&sbuf[slot][400 + q * 4];
                Bv[q*4+0] = vb.x; Bv[q*4+1] = vb.y; Bv[q*4+2] = vb.z; Bv[q*4+3] = vb.w;
                Cv[q*4+0] = vc.x; Cv[q*4+1] = vc.y; Cv[q*4+2] = vc.z; Cv[q*4+3] = vc.w;
            }

            float e[DSTATE];
            if (FAST) {
                const float r = exp2f(u * c1);
                e[0]  = r;
                e[1]  = r * r;
                e[3]  = e[1] * e[1];
                e[7]  = e[3] * e[3];
                e[15] = e[7] * e[7];
                e[2]  = e[1] * r;
                e[4]  = e[3] * r;     e[5]  = e[3] * e[1];  e[6]  = e[3] * e[2];
                e[8]  = e[7] * r;     e[9]  = e[7] * e[1];  e[10] = e[7] * e[2];
                e[11] = e[7] * e[3];  e[12] = e[7] * e[4];  e[13] = e[7] * e[5];
                e[14] = e[7] * e[6];
            } else {
#pragma unroll
                for (int s = 0; s < DSTATE; s++) e[s] = exp2f(u * cs[s]);
            }

            const float ux = u * xv;
            float y0 = 0.f, y1 = 0.f, y2 = 0.f, y3 = 0.f;
#pragma unroll
            for (int s = 0; s < DSTATE; s += 4) {
                h[s+0] = fmaf(e[s+0], h[s+0], ux * Bv[s+0]);
                h[s+1] = fmaf(e[s+1], h[s+1], ux * Bv[s+1]);
                h[s+2] = fmaf(e[s+2], h[s+2], ux * Bv[s+2]);
                h[s+3] = fmaf(e[s+3], h[s+3], ux * Bv[s+3]);
                y0 = fmaf(h[s+0], Cv[s+0], y0);
                y1 = fmaf(h[s+1], Cv[s+1], y1);
                y2 = fmaf(h[s+2], Cv[s+2], y2);
                y3 = fmaf(h[s+3], Cv[s+3], y3);
            }
            float yt = (y0 + y1) + (y2 + y3);
            yt = fmaf(xv, dpv, yt);
            const float sig = 1.f / (1.f + __expf(-zv));
            const float out = yt * (zv * sig);
            __nv_bfloat16 oh, ol;
            split_bf16(out, oh, ol);
            const size_t oidx = (rowbase + tt) * DIN + chunk * 128 + t;
            yh[oidx] = oh;
            yl[oidx] = ol;
        }
    };

    if (fast) run(std::true_type{});
    else      run(std::false_type{});
}

// ------------------------------------------------------------------- launch
extern "C" void kernel_launch(void* const* d_in, const int* in_sizes, int n_in,
                              void* d_out, int out_size)
{
    const float* x      = (const float*)d_in[0];
    const int*   mask   = (const int*)  d_in[1];
    const float* ln_g   = (const float*)d_in[2];
    const float* ln_b   = (const float*)d_in[3];
    const float* W_in   = (const float*)d_in[4];
    const float* conv_w = (const float*)d_in[5];
    const float* conv_b = (const float*)d_in[6];
    const float* W_xp   = (const float*)d_in[7];
    const float* W_dt   = (const float*)d_in[8];
    const float* b_dt   = (const float*)d_in[9];
    const float* A_log  = (const float*)d_in[10];
    const float* Dp     = (const float*)d_in[11];
    const float* W_out  = (const float*)d_in[12];
    float* out = (float*)d_out;

    static float *p_xz = nullptr, *p_xc, *p_xdbl, *p_dt;
    static __nv_bfloat16 *p_axh, *p_axl, *p_wih, *p_wil, *p_ayh, *p_ayl, *p_woh, *p_wol;
    if (!p_xz) {
        cudaGetSymbolAddress((void**)&p_xz,   g_xz);
        cudaGetSymbolAddress((void**)&p_xc,   g_xc);
        cudaGetSymbolAddress((void**)&p_xdbl, g_xdbl);
        cudaGetSymbolAddress((void**)&p_dt,   g_dt);
        cudaGetSymbolAddress((void**)&p_axh,  g_axh);
        cudaGetSymbolAddress((void**)&p_axl,  g_axl);
        cudaGetSymbolAddress((void**)&p_wih,  g_wih);
        cudaGetSymbolAddress((void**)&p_wil,  g_wil);
        cudaGetSymbolAddress((void**)&p_ayh,  g_ayh);
        cudaGetSymbolAddress((void**)&p_ayl,  g_ayl);
        cudaGetSymbolAddress((void**)&p_woh,  g_woh);
        cudaGetSymbolAddress((void**)&p_wol,  g_wol);
        cudaFuncSetAttribute(tgemm<0>, cudaFuncAttributeMaxDynamicSharedMemorySize, MM_SMEM);
        cudaFuncSetAttribute(tgemm<2>, cudaFuncAttributeMaxDynamicSharedMemorySize, MM_SMEM);
    }

    // 1. LayerNorm + mask + bf16 split pack
    ln_kernel<<<NROWS, 256>>>(x, mask, ln_g, ln_b, p_axh, p_axl);

    // 2. pack weights
    {
        long long nW = (long long)(2 * DIN) * DIMM / 8;
        pack_split<<<(unsigned)((nW + 255) / 256), 256>>>(W_in, (uint4*)p_wih, (uint4*)p_wil, nW);
        long long nO = (long long)DIMM * DIN / 8;
        pack_split<<<(unsigned)((nO + 255) / 256), 256>>>(W_out, (uint4*)p_woh, (uint4*)p_wol, nO);
    }

    // 3. in_proj on tensor pipe: xz = xn @ W_in^T   (16384 x 3072, K=768)
    {
        dim3 g((2 * DIN) / 128, NROWS / 128);
        tgemm<0><<<g, 256, MM_SMEM>>>(p_axh, p_axl, p_wih, p_wil,
                                      p_xz, 2 * DIN, DIMM, nullptr, nullptr);
    }

    // 4. depthwise causal conv + SiLU
    {
        const long long n = (long long)NROWS * DIN;
        conv_silu<<<(unsigned)((n + 255) / 256), 256>>>(p_xz, conv_w, conv_b, p_xc);
    }

    // 5. x_proj: xdbl = xc @ W_xp^T   (16384 x 80, K=1536)
    {
        dim3 g(NROWS / 128, 1);
        gemm_tn<0><<<g, 256>>>(p_xc, DIN, W_xp, DIN, p_xdbl, XPROJ,
                               XPROJ, DIN, nullptr);
    }

    // 6. dt_proj + softplus
    {
        dim3 g(NROWS / 128, DIN / 128);
        gemm_tn<1><<<g, 256>>>(p_xdbl, XPROJ, W_dt, DTRANK, p_dt, DIN,
                               DIN, DTRANK, b_dt);
    }

    // 7. selective scan + D-skip + SiLU gate -> bf16 hi/lo y
    scan_kernel<<<BB * (DIN / 128), 128>>>(p_dt, p_xc, p_xz, p_xdbl,
                                           A_log, Dp, p_ayh, p_ayl);

    // 8. out_proj on tensor pipe + residual + mask
    {
        dim3 g(DIMM / 128, NROWS / 128);
        tgemm<2><<<g, 256, MM_SMEM>>>(p_ayh, p_ayl, p_woh, p_wol,
                                      out, DIMM, DIN, x, mask);
    }
}

// round 7
// speedup vs baseline: 1.1790x; 1.0982x over previous
#include <cuda_runtime.h>
#include <cuda_bf16.h>
#include <cstdint>
#include <type_traits>

#define BB      8
#define LL      2048
#define DIMM    768
#define DIN     1536
#define DSTATE  16
#define DTRANK  48
#define NROWS   (BB * LL)              // 16384
#define XPROJ   (DTRANK + 2 * DSTATE)  // 80
#define DTPADK  64                     // dt_proj K padded 48 -> 64

// ---------------- scratch (static device globals; no allocation allowed) ---
__device__ float g_xz  [(size_t)NROWS * 2 * DIN];
__device__ float g_xc  [(size_t)NROWS * DIN];
__device__ float g_xdbl[(size_t)NROWS * XPROJ];
__device__ float g_dt  [(size_t)NROWS * DIN];

// bf16 hi/lo split operands (plain row-major)
__device__ __align__(128) __nv_bfloat16 g_axh[(size_t)NROWS * DIMM];
__device__ __align__(128) __nv_bfloat16 g_axl[(size_t)NROWS * DIMM];
__device__ __align__(128) __nv_bfloat16 g_wih[(size_t)(2*DIN) * DIMM];
__device__ __align__(128) __nv_bfloat16 g_wil[(size_t)(2*DIN) * DIMM];
__device__ __align__(128) __nv_bfloat16 g_ayh[(size_t)NROWS * DIN];
__device__ __align__(128) __nv_bfloat16 g_ayl[(size_t)NROWS * DIN];
__device__ __align__(128) __nv_bfloat16 g_woh[(size_t)DIMM * DIN];
__device__ __align__(128) __nv_bfloat16 g_wol[(size_t)DIMM * DIN];
// xc split (A of x_proj)
__device__ __align__(128) __nv_bfloat16 g_xch[(size_t)NROWS * DIN];
__device__ __align__(128) __nv_bfloat16 g_xcl[(size_t)NROWS * DIN];
// W_xp padded to 128 rows (B of x_proj)
__device__ __align__(128) __nv_bfloat16 g_wxh[(size_t)128 * DIN];
__device__ __align__(128) __nv_bfloat16 g_wxl[(size_t)128 * DIN];
// dt input split, K padded to 64 (A of dt_proj)
__device__ __align__(128) __nv_bfloat16 g_xdh[(size_t)NROWS * DTPADK];
__device__ __align__(128) __nv_bfloat16 g_xdl[(size_t)NROWS * DTPADK];
// W_dt padded K 48->64 (B of dt_proj)
__device__ __align__(128) __nv_bfloat16 g_wdh[(size_t)DIN * DTPADK];
__device__ __align__(128) __nv_bfloat16 g_wdl[(size_t)DIN * DTPADK];

// ======================== PTX helpers ============================
__device__ __forceinline__ uint32_t smem_u32(const void* p) {
    uint32_t a;
    asm("{ .reg .u64 t; cvta.to.shared.u64 t, %1; cvt.u32.u64 %0, t; }"
        : "=r"(a) : "l"(p));
    return a;
}
__device__ __forceinline__ void cp16(uint32_t dst, const void* src) {
    asm volatile("cp.async.cg.shared.global [%0], [%1], 16;" :: "r"(dst), "l"(src));
}
__device__ __forceinline__ void cp_commit() {
    asm volatile("cp.async.commit_group;" ::: "memory");
}
#define CP_WAIT(n) asm volatile("cp.async.wait_group %0;" :: "n"(n) : "memory")

#define LDSM4(r0, r1, r2, r3, addr) \
    asm volatile("ldmatrix.sync.aligned.m8n8.x4.shared.b16 {%0,%1,%2,%3}, [%4];" \
                 : "=r"(r0), "=r"(r1), "=r"(r2), "=r"(r3) : "r"(addr))
#define LDSM2(r0, r1, addr) \
    asm volatile("ldmatrix.sync.aligned.m8n8.x2.shared.b16 {%0,%1}, [%2];" \
                 : "=r"(r0), "=r"(r1) : "r"(addr))
#define MMA16816(d, a, b) \
    asm volatile("mma.sync.aligned.m16n8k16.row.col.f32.bf16.bf16.f32 " \
                 "{%0,%1,%2,%3},{%4,%5,%6,%7},{%8,%9},{%0,%1,%2,%3};" \
                 : "+f"((d)[0]), "+f"((d)[1]), "+f"((d)[2]), "+f"((d)[3]) \
                 : "r"((a)[0]), "r"((a)[1]), "r"((a)[2]), "r"((a)[3]), \
                   "r"((b)[0]), "r"((b)[1]))

__device__ __forceinline__ void split_bf16(float f, __nv_bfloat16& h, __nv_bfloat16& l) {
    h = __float2bfloat16(f);
    l = __float2bfloat16(f - __bfloat162float(h));
}
__device__ __forceinline__ float softplusf(float v) {
    return (v > 20.f) ? v : log1pf(__expf(v));
}

// =========================== pack / split kernels ==========================
__global__ void pack_split(const float* __restrict__ in,
                           uint4* __restrict__ hi, uint4* __restrict__ lo,
                           long long total8)
{
    const long long idx = (long long)blockIdx.x * blockDim.x + threadIdx.x;
    if (idx >= total8) return;
    const float* p = in + idx * 8;
    uint32_t uh[4], ul[4];
#pragma unroll
    for (int j = 0; j < 4; j++) {
        __nv_bfloat16 h0, h1, l0, l1;
        split_bf16(p[2*j],     h0, l0);
        split_bf16(p[2*j + 1], h1, l1);
        uh[j] = (uint32_t)__bfloat16_as_ushort(h0) | ((uint32_t)__bfloat16_as_ushort(h1) << 16);
        ul[j] = (uint32_t)__bfloat16_as_ushort(l0) | ((uint32_t)__bfloat16_as_ushort(l1) << 16);
    }
    hi[idx] = make_uint4(uh[0], uh[1], uh[2], uh[3]);
    lo[idx] = make_uint4(ul[0], ul[1], ul[2], ul[3]);
}

// pad-aware pack: in [R,K] -> out [Rp,Kp] (zeros outside). Small matrices only.
__global__ void pack_pad(const float* __restrict__ in,
                         __nv_bfloat16* __restrict__ hi, __nv_bfloat16* __restrict__ lo,
                         int R, int K, int Rp, int Kp)
{
    const int idx = blockIdx.x * blockDim.x + threadIdx.x;
    if (idx >= Rp * Kp) return;
    const int r = idx / Kp, k = idx % Kp;
    float v = (r < R && k < K) ? in[(size_t)r * K + k] : 0.f;
    __nv_bfloat16 h, l;
    split_bf16(v, h, l);
    hi[idx] = h;
    lo[idx] = l;
}

// ================== mma.sync bf16 3-pass split TN GEMM =====================
// (round-4/6 measured-best structure: 3-stage cp.async pipe, CP_WAIT(1),
//  LDSM2 B-fragments, loads issued after compute)
// EPI 0: store fp32.           EPI 1: softplus(acc + bias[col]) -> fp32.
// EPI 2: mask[m]*(X+acc).      EPI 3: fp32 (col<Ntot) + bf16 hi/lo of
//                                      cols<48 (zeros 48..63) into aux (ld 64).
#define MM_STG_ROW   40                 // padded row stride in bf16 elems (80B)
#define MM_BUF       (128 * 80)         // one operand buffer: 10240 B
#define MM_STAGE     (4 * MM_BUF)       // Ah, Al, Bh, Bl: 40960 B
#define MM_SMEM      (3 * MM_STAGE)     // 3 stages: 122880 B

template<int EPI>
__global__ __launch_bounds__(256, 1)
void tgemm(const __nv_bfloat16* __restrict__ Ah, const __nv_bfloat16* __restrict__ Al,
           const __nv_bfloat16* __restrict__ Bh, const __nv_bfloat16* __restrict__ Bl,
           float* __restrict__ C, int ldc, int K, int Ntot,
           const float* __restrict__ bias,
           const float* __restrict__ X, const int* __restrict__ mask,
           __nv_bfloat16* __restrict__ auxh, __nv_bfloat16* __restrict__ auxl)
{
    extern __shared__ char smem[];
    const uint32_t sBase = smem_u32(smem);

    const int tid  = threadIdx.x;
    const int wid  = tid >> 5;
    const int lane = tid & 31;
    const int wm   = wid & 1;          // 2 warps along M (64 each)
    const int wn   = wid >> 1;         // 4 warps along N (32 each)
    const int m0   = blockIdx.y * 128;
    const int n0   = blockIdx.x * 128;
    const int NK   = K / 32;

    auto load_stage = [&](int c, int slot) {
        const uint32_t sb = sBase + slot * MM_STAGE;
        const int k0 = c * 32;
#pragma unroll
        for (int h = 0; h < 2; h++) {
            const int ch  = tid + h * 256;      // 0..511
            const int row = ch >> 2;
            const int kc  = ch & 3;
            const uint32_t doff = row * 80 + kc * 16;
            const size_t goffA = (size_t)(m0 + row) * K + k0 + kc * 8;
            const size_t goffB = (size_t)(n0 + row) * K + k0 + kc * 8;
            cp16(sb + doff,               Ah + goffA);
            cp16(sb + MM_BUF + doff,      Al + goffA);
            cp16(sb + 2*MM_BUF + doff,    Bh + goffB);
            cp16(sb + 3*MM_BUF + doff,    Bl + goffB);
        }
    };

    float acc[4][4][4];
#pragma unroll
    for (int i = 0; i < 4; i++)
#pragma unroll
        for (int j = 0; j < 4; j++)
#pragma unroll
            for (int r = 0; r < 4; r++) acc[i][j][r] = 0.f;

    load_stage(0, 0); cp_commit();
    load_stage(1, 1); cp_commit();

    const int aRowB = wm * 64 + ((lane >> 3) & 1) * 8 + (lane & 7);  // + mi*16
    const int aKB   = (lane >> 4) * 8;                               // + kk*16
    const int bRowB = wn * 32 + (lane & 7);                          // + ni*8
    const int bKB   = ((lane >> 3) & 1) * 8;                         // + kk*16

    for (int c = 0; c < NK; c++) {
        CP_WAIT(1);
        __syncthreads();
        const uint32_t sb = sBase + (c % 3) * MM_STAGE;

#pragma unroll
        for (int kk = 0; kk < 2; kk++) {
            uint32_t ah[4][4], al[4][4], bh[4][2], bl[4][2];
#pragma unroll
            for (int mi = 0; mi < 4; mi++) {
                const uint32_t ad = sb + ((aRowB + mi * 16) * MM_STG_ROW
                                          + aKB + kk * 16) * 2;
                LDSM4(ah[mi][0], ah[mi][1], ah[mi][2], ah[mi][3], ad);
                LDSM4(al[mi][0], al[mi][1], al[mi][2], al[mi][3], ad + MM_BUF);
            }
#pragma unroll
            for (int ni = 0; ni < 4; ni++) {
                const uint32_t bd = sb + 2*MM_BUF + ((bRowB + ni * 8) * MM_STG_ROW
                                                     + bKB + kk * 16) * 2;
                LDSM2(bh[ni][0], bh[ni][1], bd);
                LDSM2(bl[ni][0], bl[ni][1], bd + MM_BUF);
            }
#pragma unroll
            for (int mi = 0; mi < 4; mi++)
#pragma unroll
                for (int ni = 0; ni < 4; ni++) {
                    MMA16816(acc[mi][ni], ah[mi], bh[ni]);
                    MMA16816(acc[mi][ni], ah[mi], bl[ni]);
                    MMA16816(acc[mi][ni], al[mi], bh[ni]);
                }
        }

        if (c + 2 < NK) load_stage(c + 2, (c + 2) % 3);
        cp_commit();
    }

    // ------------------------------- epilogue -------------------------------
    const int rq = lane >> 2;
    const int cq = (lane & 3) * 2;
#pragma unroll
    for (int mi = 0; mi < 4; mi++) {
        const int r0 = m0 + wm * 64 + mi * 16 + rq;
        const int r1 = r0 + 8;
        float mf0 = 1.f, mf1 = 1.f;
        if (EPI == 2) { mf0 = (float)mask[r0]; mf1 = (float)mask[r1]; }
#pragma unroll
        for (int ni = 0; ni < 4; ni++) {
            const int cc = n0 + wn * 32 + ni * 8 + cq;
            float v0 = acc[mi][ni][0], v1 = acc[mi][ni][1];
            float v2 = acc[mi][ni][2], v3 = acc[mi][ni][3];
            if (EPI == 1) {
                const float b0 = bias[cc], b1 = bias[cc + 1];
                v0 = softplusf(v0 + b0); v1 = softplusf(v1 + b1);
                v2 = softplusf(v2 + b0); v3 = softplusf(v3 + b1);
            } else if (EPI == 2) {
                const float* x0 = X + (size_t)r0 * ldc + cc;
                const float* x1 = X + (size_t)r1 * ldc + cc;
                v0 = mf0 * (x0[0] + v0); v1 = mf0 * (x0[1] + v1);
                v2 = mf1 * (x1[0] + v2); v3 = mf1 * (x1[1] + v3);
            }
            if (EPI != 3 || cc + 1 < Ntot) {   // cc even, Ntot=80: both or none
                *(float2*)(C + (size_t)r0 * ldc + cc) = make_float2(v0, v1);
                *(float2*)(C + (size_t)r1 * ldc + cc) = make_float2(v2, v3);
            }
            if (EPI == 3) {
#pragma unroll
                for (int j = 0; j < 2; j++) {
                    const int col = cc + j;
                    if (col < DTPADK) {
                        const float a0 = (col < DTRANK) ? ((j == 0) ? v0 : v1) : 0.f;
                        const float a1 = (col < DTRANK) ? ((j == 0) ? v2 : v3) : 0.f;
                        __nv_bfloat16 h, l;
                        split_bf16(a0, h, l);
                        auxh[(size_t)r0 * DTPADK + col] = h;
                        auxl[(size_t)r0 * DTPADK + col] = l;
                        split_bf16(a1, h, l);
                        auxh[(size_t)r1 * DTPADK + col] = h;
                        auxl[(size_t)r1 * DTPADK + col] = l;
                    }
                }
            }
        }
    }
}

// --------------------------- LayerNorm + fused bf16 split pack -------------
__global__ void ln_kernel(const float* __restrict__ x,
                          const int*   __restrict__ mask,
                          const float* __restrict__ g,
                          const float* __restrict__ b,
                          __nv_bfloat16* __restrict__ xh,
                          __nv_bfloat16* __restrict__ xl)
{
    const int row = blockIdx.x;
    const int t   = threadIdx.x;
    const float* xr = x + (size_t)row * DIMM;

    float v[3];
    float s = 0.f, s2 = 0.f;
#pragma unroll
    for (int j = 0; j < 3; j++) {
        v[j] = xr[t + j * 256];
        s  += v[j];
        s2 += v[j] * v[j];
    }
    __shared__ float red[2][8];
#pragma unroll
    for (int o = 16; o > 0; o >>= 1) {
        s  += __shfl_xor_sync(0xffffffffu, s,  o);
        s2 += __shfl_xor_sync(0xffffffffu, s2, o);
    }
    if ((t & 31) == 0) { red[0][t >> 5] = s; red[1][t >> 5] = s2; }
    __syncthreads();
    float ts = 0.f, ts2 = 0.f;
#pragma unroll
    for (int j = 0; j < 8; j++) { ts += red[0][j]; ts2 += red[1][j]; }

    const float mu   = ts * (1.0f / DIMM);
    const float var  = ts2 * (1.0f / DIMM) - mu * mu;
    const float rstd = rsqrtf(var + 1e-5f);
    const float mf   = (float)mask[row];

#pragma unroll
    for (int j = 0; j < 3; j++) {
        const int c = t + j * 256;
        const float o = ((v[j] - mu) * rstd * g[c] + b[c]) * mf;
        __nv_bfloat16 h, l;
        split_bf16(o, h, l);
        xh[(size_t)row * DIMM + c] = h;
        xl[(size_t)row * DIMM + c] = l;
    }
}

// --------------- depthwise causal conv4 + SiLU + bf16 split ----------------
__global__ void conv_silu(const float* __restrict__ xz,
                          const float* __restrict__ w,
                          const float* __restrict__ bias,
                          float* __restrict__ xc,
                          __nv_bfloat16* __restrict__ xch,
                          __nv_bfloat16* __restrict__ xcl)
{
    const long long idx = (long long)blockIdx.x * blockDim.x + threadIdx.x;
    if (idx >= (long long)NROWS * DIN) return;
    const int d = (int)(idx % DIN);
    const int i = (int)(idx / DIN);
    const int l = i % LL;

    float s = bias[d];
    const float* wp = w + d * 4;
#pragma unroll
    for (int j = 0; j < 4; j++) {
        const int ll = l - 3 + j;
        if (ll >= 0)
            s = fmaf(wp[j], xz[(size_t)(i - 3 + j) * (2 * DIN) + d], s);
    }
    const float sig = 1.f / (1.f + __expf(-s));
    const float o = s * sig;
    xc[idx] = o;
    __nv_bfloat16 h, l2;
    split_bf16(o, h, l2);
    xch[idx] = h;
    xcl[idx] = l2;
}

// ------------------------------------------------------------ selective scan
#define SSTAGE 8
#define STAGEF 416   // 128 dt + 128 xc + 128 z + 32 bc

__global__ __launch_bounds__(128)
void scan_kernel(const float* __restrict__ dt,
                 const float* __restrict__ xc,
                 const float* __restrict__ xz,
                 const float* __restrict__ xdbl,
                 const float* __restrict__ A_log,
                 const float* __restrict__ Dp,
                 __nv_bfloat16* __restrict__ yh,
                 __nv_bfloat16* __restrict__ yl)
{
    __shared__ float sbuf[SSTAGE][STAGEF];

    const int b     = blockIdx.x / (DIN / 128);
    const int chunk = blockIdx.x % (DIN / 128);
    const int t     = threadIdx.x;
    const int d     = chunk * 128 + t;
    const size_t rowbase = (size_t)b * LL;

    float a[DSTATE];
#pragma unroll
    for (int s = 0; s < DSTATE; s++) a[s] = -__expf(A_log[d * DSTATE + s]);

    bool fast = true;
#pragma unroll
    for (int s = 1; s < DSTATE; s++) {
        const float ideal = a[0] * (float)(s + 1);
        if (fabsf(a[s] - ideal) > 1e-4f * fabsf(ideal)) fast = false;
    }
    fast = __syncthreads_and(fast ? 1 : 0);

    const float LOG2E = 1.44269504088896f;
    const float c1 = a[0] * LOG2E;
    float cs[DSTATE];
#pragma unroll
    for (int s = 0; s < DSTATE; s++) cs[s] = a[s] * LOG2E;
    const float dpv = Dp[d];

    float h[DSTATE];
#pragma unroll
    for (int s = 0; s < DSTATE; s++) h[s] = 0.f;

    const int role = t >> 5;
    const int lane = t & 31;

    auto issue = [&](int tt) {
        const int slot = tt & (SSTAGE - 1);
        const size_t row = rowbase + tt;
        const float* gp = nullptr;
        int soff = 0;
        bool active = true;
        if (role == 0)      { gp = dt + row * DIN + chunk * 128 + lane * 4;                soff = lane * 4; }
        else if (role == 1) { gp = xc + row * DIN + chunk * 128 + lane * 4;                soff = 128 + lane * 4; }
        else if (role == 2) { gp = xz + row * (2 * DIN) + DIN + chunk * 128 + lane * 4;    soff = 256 + lane * 4; }
        else                { active = (lane < 8);
                              gp = xdbl + row * XPROJ + DTRANK + lane * 4;                 soff = 384 + lane * 4; }
        if (active)
            cp16((uint32_t)__cvta_generic_to_shared(&sbuf[slot][soff]), gp);
        cp_commit();
    };

    for (int tt = 0; tt < SSTAGE - 1; tt++) issue(tt);

    auto run = [&](auto fastc) {
        constexpr bool FAST = decltype(fastc)::value;
        for (int tt = 0; tt < LL; tt++) {
            CP_WAIT(SSTAGE - 2);
            __syncthreads();
            if (tt + SSTAGE - 1 < LL) issue(tt + SSTAGE - 1);

            const int slot = tt & (SSTAGE - 1);
            const float u  = sbuf[slot][t];
            const float xv = sbuf[slot][128 + t];
            const float zv = sbuf[slot][256 + t];
            float Bv[DSTATE], Cv[DSTATE];
#pragma unroll
            for (int q = 0; q < 4; q++) {
                float4 vb = *(const float4*)&sbuf[slot][384 + q * 4];
                float4 vc = *(const float4*)&sbuf[slot][400 + q * 4];
                Bv[q*4+0] = vb.x; Bv[q*4+1] = vb.y; Bv[q*4+2] = vb.z; Bv[q*4+3] = vb.w;
                Cv[q*4+0] = vc.x; Cv[q*4+1] = vc.y; Cv[q*4+2] = vc.z; Cv[q*4+3] = vc.w;
            }

            float e[DSTATE];
            if (FAST) {
                const float r = exp2f(u * c1);
                e[0]  = r;
                e[1]  = r * r;
                e[3]  = e[1] * e[1];
                e[7]  = e[3] * e[3];
                e[15] = e[7] * e[7];
                e[2]  = e[1] * r;
                e[4]  = e[3] * r;     e[5]  = e[3] * e[1];  e[6]  = e[3] * e[2];
                e[8]  = e[7] * r;     e[9]  = e[7] * e[1];  e[10] = e[7] * e[2];
                e[11] = e[7] * e[3];  e[12] = e[7] * e[4];  e[13] = e[7] * e[5];
                e[14] = e[7] * e[6];
            } else {
#pragma unroll
                for (int s = 0; s < DSTATE; s++) e[s] = exp2f(u * cs[s]);
            }

            const float ux = u * xv;
            float y0 = 0.f, y1 = 0.f, y2 = 0.f, y3 = 0.f;
#pragma unroll
            for (int s = 0; s < DSTATE; s += 4) {
                h[s+0] = fmaf(e[s+0], h[s+0], ux * Bv[s+0]);
                h[s+1] = fmaf(e[s+1], h[s+1], ux * Bv[s+1]);
                h[s+2] = fmaf(e[s+2], h[s+2], ux * Bv[s+2]);
                h[s+3] = fmaf(e[s+3], h[s+3], ux * Bv[s+3]);
                y0 = fmaf(h[s+0], Cv[s+0], y0);
                y1 = fmaf(h[s+1], Cv[s+1], y1);
                y2 = fmaf(h[s+2], Cv[s+2], y2);
                y3 = fmaf(h[s+3], Cv[s+3], y3);
            }
            float yt = (y0 + y1) + (y2 + y3);
            yt = fmaf(xv, dpv, yt);
            const float sig = 1.f / (1.f + __expf(-zv));
            const float out = yt * (zv * sig);
            __nv_bfloat16 oh, ol;
            split_bf16(out, oh, ol);
            const size_t oidx = (rowbase + tt) * DIN + chunk * 128 + t;
            yh[oidx] = oh;
            yl[oidx] = ol;
        }
    };

    if (fast) run(std::true_type{});
    else      run(std::false_type{});
}

// ------------------------------------------------------------------- launch
extern "C" void kernel_launch(void* const* d_in, const int* in_sizes, int n_in,
                              void* d_out, int out_size)
{
    const float* x      = (const float*)d_in[0];
    const int*   mask   = (const int*)  d_in[1];
    const float* ln_g   = (const float*)d_in[2];
    const float* ln_b   = (const float*)d_in[3];
    const float* W_in   = (const float*)d_in[4];
    const float* conv_w = (const float*)d_in[5];
    const float* conv_b = (const float*)d_in[6];
    const float* W_xp   = (const float*)d_in[7];
    const float* W_dt   = (const float*)d_in[8];
    const float* b_dt   = (const float*)d_in[9];
    const float* A_log  = (const float*)d_in[10];
    const float* Dp     = (const float*)d_in[11];
    const float* W_out  = (const float*)d_in[12];
    float* out = (float*)d_out;

    static float *p_xz = nullptr, *p_xc, *p_xdbl, *p_dt;
    static __nv_bfloat16 *p_axh, *p_axl, *p_wih, *p_wil, *p_ayh, *p_ayl, *p_woh, *p_wol;
    static __nv_bfloat16 *p_xch, *p_xcl, *p_wxh, *p_wxl, *p_xdh, *p_xdl, *p_wdh, *p_wdl;
    if (!p_xz) {
        cudaGetSymbolAddress((void**)&p_xz,   g_xz);
        cudaGetSymbolAddress((void**)&p_xc,   g_xc);
        cudaGetSymbolAddress((void**)&p_xdbl, g_xdbl);
        cudaGetSymbolAddress((void**)&p_dt,   g_dt);
        cudaGetSymbolAddress((void**)&p_axh,  g_axh);
        cudaGetSymbolAddress((void**)&p_axl,  g_axl);
        cudaGetSymbolAddress((void**)&p_wih,  g_wih);
        cudaGetSymbolAddress((void**)&p_wil,  g_wil);
        cudaGetSymbolAddress((void**)&p_ayh,  g_ayh);
        cudaGetSymbolAddress((void**)&p_ayl,  g_ayl);
        cudaGetSymbolAddress((void**)&p_woh,  g_woh);
        cudaGetSymbolAddress((void**)&p_wol,  g_wol);
        cudaGetSymbolAddress((void**)&p_xch,  g_xch);
        cudaGetSymbolAddress((void**)&p_xcl,  g_xcl);
        cudaGetSymbolAddress((void**)&p_wxh,  g_wxh);
        cudaGetSymbolAddress((void**)&p_wxl,  g_wxl);
        cudaGetSymbolAddress((void**)&p_xdh,  g_xdh);
        cudaGetSymbolAddress((void**)&p_xdl,  g_xdl);
        cudaGetSymbolAddress((void**)&p_wdh,  g_wdh);
        cudaGetSymbolAddress((void**)&p_wdl,  g_wdl);
        cudaFuncSetAttribute(tgemm<0>, cudaFuncAttributeMaxDynamicSharedMemorySize, MM_SMEM);
        cudaFuncSetAttribute(tgemm<1>, cudaFuncAttributeMaxDynamicSharedMemorySize, MM_SMEM);
        cudaFuncSetAttribute(tgemm<2>, cudaFuncAttributeMaxDynamicSharedMemorySize, MM_SMEM);
        cudaFuncSetAttribute(tgemm<3>, cudaFuncAttributeMaxDynamicSharedMemorySize, MM_SMEM);
    }

    // 1. LayerNorm + mask + bf16 split pack
    ln_kernel<<<NROWS, 256>>>(x, mask, ln_g, ln_b, p_axh, p_axl);

    // 2. pack weights
    {
        long long nW = (long long)(2 * DIN) * DIMM / 8;
        pack_split<<<(unsigned)((nW + 255) / 256), 256>>>(W_in, (uint4*)p_wih, (uint4*)p_wil, nW);
        long long nO = (long long)DIMM * DIN / 8;
        pack_split<<<(unsigned)((nO + 255) / 256), 256>>>(W_out, (uint4*)p_woh, (uint4*)p_wol, nO);
        // W_xp padded [80,1536] -> [128,1536]
        pack_pad<<<(128 * DIN + 255) / 256, 256>>>(W_xp, p_wxh, p_wxl, XPROJ, DIN, 128, DIN);
        // W_dt padded [1536,48] -> [1536,64]
        pack_pad<<<(DIN * DTPADK + 255) / 256, 256>>>(W_dt, p_wdh, p_wdl, DIN, DTRANK, DIN, DTPADK);
    }

    // 3. in_proj: xz = xn @ W_in^T   (16384 x 3072, K=768)
    {
        dim3 g((2 * DIN) / 128, NROWS / 128);
        tgemm<0><<<g, 256, MM_SMEM>>>(p_axh, p_axl, p_wih, p_wil,
                                      p_xz, 2 * DIN, DIMM, 2 * DIN,
                                      nullptr, nullptr, nullptr, nullptr, nullptr);
    }

    // 4. depthwise causal conv + SiLU (+ bf16 split of xc)
    {
        const long long n = (long long)NROWS * DIN;
        conv_silu<<<(unsigned)((n + 255) / 256), 256>>>(p_xz, conv_w, conv_b,
                                                        p_xc, p_xch, p_xcl);
    }

    // 5. x_proj on tensor: xdbl = xc @ W_xp^T (N pad 80->128, K=1536)
    //    epilogue also writes dt-input bf16 split [NROWS x 64]
    {
        dim3 g(1, NROWS / 128);
        tgemm<3><<<g, 256, MM_SMEM>>>(p_xch, p_xcl, p_wxh, p_wxl,
                                      p_xdbl, XPROJ, DIN, XPROJ,
                                      nullptr, nullptr, nullptr, p_xdh, p_xdl);
    }

    // 6. dt_proj on tensor + softplus: dt = softplus(dt_in @ W_dt^T + b_dt)
    //    (K padded 48->64)
    {
        dim3 g(DIN / 128, NROWS / 128);
        tgemm<1><<<g, 256, MM_SMEM>>>(p_xdh, p_xdl, p_wdh, p_wdl,
                                      p_dt, DIN, DTPADK, DIN,
                                      b_dt, nullptr, nullptr, nullptr, nullptr);
    }

    // 7. selective scan + D-skip + SiLU gate -> bf16 hi/lo y
    scan_kernel<<<BB * (DIN / 128), 128>>>(p_dt, p_xc, p_xz, p_xdbl,
                                           A_log, Dp, p_ayh, p_ayl);

    // 8. out_proj + residual + mask
    {
        dim3 g(DIMM / 128, NROWS / 128);
        tgemm<2><<<g, 256, MM_SMEM>>>(p_ayh, p_ayl, p_woh, p_wol,
                                      out, DIMM, DIN, DIMM,
                                      nullptr, x, mask, nullptr, nullptr);
    }
}

// round 8
// speedup vs baseline: 1.3983x; 1.1860x over previous
#include <cuda_runtime.h>
#include <cuda_bf16.h>
#include <cstdint>
#include <type_traits>

#define BB      8
#define LL      2048
#define DIMM    768
#define DIN     1536
#define DSTATE  16
#define DTRANK  48
#define NROWS   (BB * LL)              // 16384
#define XPROJ   (DTRANK + 2 * DSTATE)  // 80
#define DTPADK  64                     // dt_proj K padded 48 -> 64
#define NSEG    8                      // scan segments
#define SEGL    (LL / NSEG)            // 256 steps per segment

// ---------------- scratch (static device globals; no allocation allowed) ---
__device__ float g_xz  [(size_t)NROWS * 2 * DIN];
__device__ float g_xc  [(size_t)NROWS * DIN];
__device__ float g_xdbl[(size_t)NROWS * XPROJ];
__device__ float g_dt  [(size_t)NROWS * DIN];
// segmented-scan state buffers: layout [b][seg][s][DIN]
__device__ float g_Hseg[(size_t)BB * NSEG * DSTATE * DIN];
__device__ float g_Eseg[(size_t)BB * NSEG * DSTATE * DIN];
__device__ float g_H0  [(size_t)BB * NSEG * DSTATE * DIN];

// bf16 hi/lo split operands (plain row-major)
__device__ __align__(128) __nv_bfloat16 g_axh[(size_t)NROWS * DIMM];
__device__ __align__(128) __nv_bfloat16 g_axl[(size_t)NROWS * DIMM];
__device__ __align__(128) __nv_bfloat16 g_wih[(size_t)(2*DIN) * DIMM];
__device__ __align__(128) __nv_bfloat16 g_wil[(size_t)(2*DIN) * DIMM];
__device__ __align__(128) __nv_bfloat16 g_ayh[(size_t)NROWS * DIN];
__device__ __align__(128) __nv_bfloat16 g_ayl[(size_t)NROWS * DIN];
__device__ __align__(128) __nv_bfloat16 g_woh[(size_t)DIMM * DIN];
__device__ __align__(128) __nv_bfloat16 g_wol[(size_t)DIMM * DIN];
// xc split (A of x_proj)
__device__ __align__(128) __nv_bfloat16 g_xch[(size_t)NROWS * DIN];
__device__ __align__(128) __nv_bfloat16 g_xcl[(size_t)NROWS * DIN];
// W_xp padded to 128 rows (B of x_proj)
__device__ __align__(128) __nv_bfloat16 g_wxh[(size_t)128 * DIN];
__device__ __align__(128) __nv_bfloat16 g_wxl[(size_t)128 * DIN];
// dt input split, K padded to 64 (A of dt_proj)
__device__ __align__(128) __nv_bfloat16 g_xdh[(size_t)NROWS * DTPADK];
__device__ __align__(128) __nv_bfloat16 g_xdl[(size_t)NROWS * DTPADK];
// W_dt padded K 48->64 (B of dt_proj)
__device__ __align__(128) __nv_bfloat16 g_wdh[(size_t)DIN * DTPADK];
__device__ __align__(128) __nv_bfloat16 g_wdl[(size_t)DIN * DTPADK];

// ======================== PTX helpers ============================
__device__ __forceinline__ uint32_t smem_u32(const void* p) {
    uint32_t a;
    asm("{ .reg .u64 t; cvta.to.shared.u64 t, %1; cvt.u32.u64 %0, t; }"
        : "=r"(a) : "l"(p));
    return a;
}
__device__ __forceinline__ void cp16(uint32_t dst, const void* src) {
    asm volatile("cp.async.cg.shared.global [%0], [%1], 16;" :: "r"(dst), "l"(src));
}
__device__ __forceinline__ void cp_commit() {
    asm volatile("cp.async.commit_group;" ::: "memory");
}
#define CP_WAIT(n) asm volatile("cp.async.wait_group %0;" :: "n"(n) : "memory")

#define LDSM4(r0, r1, r2, r3, addr) \
    asm volatile("ldmatrix.sync.aligned.m8n8.x4.shared.b16 {%0,%1,%2,%3}, [%4];" \
                 : "=r"(r0), "=r"(r1), "=r"(r2), "=r"(r3) : "r"(addr))
#define LDSM2(r0, r1, addr) \
    asm volatile("ldmatrix.sync.aligned.m8n8.x2.shared.b16 {%0,%1}, [%2];" \
                 : "=r"(r0), "=r"(r1) : "r"(addr))
#define MMA16816(d, a, b) \
    asm volatile("mma.sync.aligned.m16n8k16.row.col.f32.bf16.bf16.f32 " \
                 "{%0,%1,%2,%3},{%4,%5,%6,%7},{%8,%9},{%0,%1,%2,%3};" \
                 : "+f"((d)[0]), "+f"((d)[1]), "+f"((d)[2]), "+f"((d)[3]) \
                 : "r"((a)[0]), "r"((a)[1]), "r"((a)[2]), "r"((a)[3]), \
                   "r"((b)[0]), "r"((b)[1]))

__device__ __forceinline__ void split_bf16(float f, __nv_bfloat16& h, __nv_bfloat16& l) {
    h = __float2bfloat16(f);
    l = __float2bfloat16(f - __bfloat162float(h));
}
__device__ __forceinline__ float softplusf(float v) {
    return (v > 20.f) ? v : log1pf(__expf(v));
}

// =========================== pack / split kernels ==========================
__global__ void pack_split(const float* __restrict__ in,
                           uint4* __restrict__ hi, uint4* __restrict__ lo,
                           long long total8)
{
    const long long idx = (long long)blockIdx.x * blockDim.x + threadIdx.x;
    if (idx >= total8) return;
    const float* p = in + idx * 8;
    uint32_t uh[4], ul[4];
#pragma unroll
    for (int j = 0; j < 4; j++) {
        __nv_bfloat16 h0, h1, l0, l1;
        split_bf16(p[2*j],     h0, l0);
        split_bf16(p[2*j + 1], h1, l1);
        uh[j] = (uint32_t)__bfloat16_as_ushort(h0) | ((uint32_t)__bfloat16_as_ushort(h1) << 16);
        ul[j] = (uint32_t)__bfloat16_as_ushort(l0) | ((uint32_t)__bfloat16_as_ushort(l1) << 16);
    }
    hi[idx] = make_uint4(uh[0], uh[1], uh[2], uh[3]);
    lo[idx] = make_uint4(ul[0], ul[1], ul[2], ul[3]);
}

// pad-aware pack: in [R,K] -> out [Rp,Kp] (zeros outside). Small matrices only.
__global__ void pack_pad(const float* __restrict__ in,
                         __nv_bfloat16* __restrict__ hi, __nv_bfloat16* __restrict__ lo,
                         int R, int K, int Rp, int Kp)
{
    const int idx = blockIdx.x * blockDim.x + threadIdx.x;
    if (idx >= Rp * Kp) return;
    const int r = idx / Kp, k = idx % Kp;
    float v = (r < R && k < K) ? in[(size_t)r * K + k] : 0.f;
    __nv_bfloat16 h, l;
    split_bf16(v, h, l);
    hi[idx] = h;
    lo[idx] = l;
}

// ================== mma.sync bf16 3-pass split TN GEMM =====================
// EPI 0: store fp32.           EPI 1: softplus(acc + bias[col]) -> fp32.
// EPI 2: mask[m]*(X+acc).      EPI 3: fp32 (col<Ntot) + bf16 hi/lo of
//                                      cols<48 (zeros 48..63) into aux (ld 64).
#define MM_STG_ROW   40
#define MM_BUF       (128 * 80)
#define MM_STAGE     (4 * MM_BUF)
#define MM_SMEM      (3 * MM_STAGE)

template<int EPI>
__global__ __launch_bounds__(256, 1)
void tgemm(const __nv_bfloat16* __restrict__ Ah, const __nv_bfloat16* __restrict__ Al,
           const __nv_bfloat16* __restrict__ Bh, const __nv_bfloat16* __restrict__ Bl,
           float* __restrict__ C, int ldc, int K, int Ntot,
           const float* __restrict__ bias,
           const float* __restrict__ X, const int* __restrict__ mask,
           __nv_bfloat16* __restrict__ auxh, __nv_bfloat16* __restrict__ auxl)
{
    extern __shared__ char smem[];
    const uint32_t sBase = smem_u32(smem);

    const int tid  = threadIdx.x;
    const int wid  = tid >> 5;
    const int lane = tid & 31;
    const int wm   = wid & 1;
    const int wn   = wid >> 1;
    const int m0   = blockIdx.y * 128;
    const int n0   = blockIdx.x * 128;
    const int NK   = K / 32;

    auto load_stage = [&](int c, int slot) {
        const uint32_t sb = sBase + slot * MM_STAGE;
        const int k0 = c * 32;
#pragma unroll
        for (int h = 0; h < 2; h++) {
            const int ch  = tid + h * 256;
            const int row = ch >> 2;
            const int kc  = ch & 3;
            const uint32_t doff = row * 80 + kc * 16;
            const size_t goffA = (size_t)(m0 + row) * K + k0 + kc * 8;
            const size_t goffB = (size_t)(n0 + row) * K + k0 + kc * 8;
            cp16(sb + doff,               Ah + goffA);
            cp16(sb + MM_BUF + doff,      Al + goffA);
            cp16(sb + 2*MM_BUF + doff,    Bh + goffB);
            cp16(sb + 3*MM_BUF + doff,    Bl + goffB);
        }
    };

    float acc[4][4][4];
#pragma unroll
    for (int i = 0; i < 4; i++)
#pragma unroll
        for (int j = 0; j < 4; j++)
#pragma unroll
            for (int r = 0; r < 4; r++) acc[i][j][r] = 0.f;

    load_stage(0, 0); cp_commit();
    load_stage(1, 1); cp_commit();

    const int aRowB = wm * 64 + ((lane >> 3) & 1) * 8 + (lane & 7);
    const int aKB   = (lane >> 4) * 8;
    const int bRowB = wn * 32 + (lane & 7);
    const int bKB   = ((lane >> 3) & 1) * 8;

    for (int c = 0; c < NK; c++) {
        CP_WAIT(1);
        __syncthreads();
        const uint32_t sb = sBase + (c % 3) * MM_STAGE;

#pragma unroll
        for (int kk = 0; kk < 2; kk++) {
            uint32_t ah[4][4], al[4][4], bh[4][2], bl[4][2];
#pragma unroll
            for (int mi = 0; mi < 4; mi++) {
                const uint32_t ad = sb + ((aRowB + mi * 16) * MM_STG_ROW
                                          + aKB + kk * 16) * 2;
                LDSM4(ah[mi][0], ah[mi][1], ah[mi][2], ah[mi][3], ad);
                LDSM4(al[mi][0], al[mi][1], al[mi][2], al[mi][3], ad + MM_BUF);
            }
#pragma unroll
            for (int ni = 0; ni < 4; ni++) {
                const uint32_t bd = sb + 2*MM_BUF + ((bRowB + ni * 8) * MM_STG_ROW
                                                     + bKB + kk * 16) * 2;
                LDSM2(bh[ni][0], bh[ni][1], bd);
                LDSM2(bl[ni][0], bl[ni][1], bd + MM_BUF);
            }
#pragma unroll
            for (int mi = 0; mi < 4; mi++)
#pragma unroll
                for (int ni = 0; ni < 4; ni++) {
                    MMA16816(acc[mi][ni], ah[mi], bh[ni]);
                    MMA16816(acc[mi][ni], ah[mi], bl[ni]);
                    MMA16816(acc[mi][ni], al[mi], bh[ni]);
                }
        }

        if (c + 2 < NK) load_stage(c + 2, (c + 2) % 3);
        cp_commit();
    }

    const int rq = lane >> 2;
    const int cq = (lane & 3) * 2;
#pragma unroll
    for (int mi = 0; mi < 4; mi++) {
        const int r0 = m0 + wm * 64 + mi * 16 + rq;
        const int r1 = r0 + 8;
        float mf0 = 1.f, mf1 = 1.f;
        if (EPI == 2) { mf0 = (float)mask[r0]; mf1 = (float)mask[r1]; }
#pragma unroll
        for (int ni = 0; ni < 4; ni++) {
            const int cc = n0 + wn * 32 + ni * 8 + cq;
            float v0 = acc[mi][ni][0], v1 = acc[mi][ni][1];
            float v2 = acc[mi][ni][2], v3 = acc[mi][ni][3];
            if (EPI == 1) {
                const float b0 = bias[cc], b1 = bias[cc + 1];
                v0 = softplusf(v0 + b0); v1 = softplusf(v1 + b1);
                v2 = softplusf(v2 + b0); v3 = softplusf(v3 + b1);
            } else if (EPI == 2) {
                const float* x0 = X + (size_t)r0 * ldc + cc;
                const float* x1 = X + (size_t)r1 * ldc + cc;
                v0 = mf0 * (x0[0] + v0); v1 = mf0 * (x0[1] + v1);
                v2 = mf1 * (x1[0] + v2); v3 = mf1 * (x1[1] + v3);
            }
            if (EPI != 3 || cc + 1 < Ntot) {
                *(float2*)(C + (size_t)r0 * ldc + cc) = make_float2(v0, v1);
                *(float2*)(C + (size_t)r1 * ldc + cc) = make_float2(v2, v3);
            }
            if (EPI == 3) {
#pragma unroll
                for (int j = 0; j < 2; j++) {
                    const int col = cc + j;
                    if (col < DTPADK) {
                        const float a0 = (col < DTRANK) ? ((j == 0) ? v0 : v1) : 0.f;
                        const float a1 = (col < DTRANK) ? ((j == 0) ? v2 : v3) : 0.f;
                        __nv_bfloat16 h, l;
                        split_bf16(a0, h, l);
                        auxh[(size_t)r0 * DTPADK + col] = h;
                        auxl[(size_t)r0 * DTPADK + col] = l;
                        split_bf16(a1, h, l);
                        auxh[(size_t)r1 * DTPADK + col] = h;
                        auxl[(size_t)r1 * DTPADK + col] = l;
                    }
                }
            }
        }
    }
}

// --------------------------- LayerNorm + fused bf16 split pack -------------
__global__ void ln_kernel(const float* __restrict__ x,
                          const int*   __restrict__ mask,
                          const float* __restrict__ g,
                          const float* __restrict__ b,
                          __nv_bfloat16* __restrict__ xh,
                          __nv_bfloat16* __restrict__ xl)
{
    const int row = blockIdx.x;
    const int t   = threadIdx.x;
    const float* xr = x + (size_t)row * DIMM;

    float v[3];
    float s = 0.f, s2 = 0.f;
#pragma unroll
    for (int j = 0; j < 3; j++) {
        v[j] = xr[t + j * 256];
        s  += v[j];
        s2 += v[j] * v[j];
    }
    __shared__ float red[2][8];
#pragma unroll
    for (int o = 16; o > 0; o >>= 1) {
        s  += __shfl_xor_sync(0xffffffffu, s,  o);
        s2 += __shfl_xor_sync(0xffffffffu, s2, o);
    }
    if ((t & 31) == 0) { red[0][t >> 5] = s; red[1][t >> 5] = s2; }
    __syncthreads();
    float ts = 0.f, ts2 = 0.f;
#pragma unroll
    for (int j = 0; j < 8; j++) { ts += red[0][j]; ts2 += red[1][j]; }

    const float mu   = ts * (1.0f / DIMM);
    const float var  = ts2 * (1.0f / DIMM) - mu * mu;
    const float rstd = rsqrtf(var + 1e-5f);
    const float mf   = (float)mask[row];

#pragma unroll
    for (int j = 0; j < 3; j++) {
        const int c = t + j * 256;
        const float o = ((v[j] - mu) * rstd * g[c] + b[c]) * mf;
        __nv_bfloat16 h, l;
        split_bf16(o, h, l);
        xh[(size_t)row * DIMM + c] = h;
        xl[(size_t)row * DIMM + c] = l;
    }
}

// --------------- depthwise causal conv4 + SiLU + bf16 split ----------------
__global__ void conv_silu(const float* __restrict__ xz,
                          const float* __restrict__ w,
                          const float* __restrict__ bias,
                          float* __restrict__ xc,
                          __nv_bfloat16* __restrict__ xch,
                          __nv_bfloat16* __restrict__ xcl)
{
    const long long idx = (long long)blockIdx.x * blockDim.x + threadIdx.x;
    if (idx >= (long long)NROWS * DIN) return;
    const int d = (int)(idx % DIN);
    const int i = (int)(idx / DIN);
    const int l = i % LL;

    float s = bias[d];
    const float* wp = w + d * 4;
#pragma unroll
    for (int j = 0; j < 4; j++) {
        const int ll = l - 3 + j;
        if (ll >= 0)
            s = fmaf(wp[j], xz[(size_t)(i - 3 + j) * (2 * DIN) + d], s);
    }
    const float sig = 1.f / (1.f + __expf(-s));
    const float o = s * sig;
    xc[idx] = o;
    __nv_bfloat16 h, l2;
    split_bf16(o, h, l2);
    xch[idx] = h;
    xcl[idx] = l2;
}

// ======================= segmented selective scan ==========================
// PHASE 0: local scan from h=0 over SEGL steps; store Hseg (final state) and
//          Eseg (prod of decays), layout [b][seg][s][DIN].
// PHASE 1: local scan seeded with H0; emit gated bf16 hi/lo y.
#define SSTAGE 8
#define STAGEF 416   // 128 dt + 128 xc + 128 z + 32 bc

template<int PHASE>
__global__ __launch_bounds__(128)
void scan_seg(const float* __restrict__ dt,
              const float* __restrict__ xc,
              const float* __restrict__ xz,
              const float* __restrict__ xdbl,
              const float* __restrict__ A_log,
              const float* __restrict__ Dp,
              float* __restrict__ Hseg,
              float* __restrict__ Eseg,
              const float* __restrict__ H0,
              __nv_bfloat16* __restrict__ yh,
              __nv_bfloat16* __restrict__ yl)
{
    __shared__ float sbuf[SSTAGE][STAGEF];

    const int bx    = blockIdx.x;
    const int b     = bx / ((DIN / 128) * NSEG);
    const int rem   = bx % ((DIN / 128) * NSEG);
    const int chunk = rem / NSEG;
    const int seg   = rem % NSEG;
    const int t     = threadIdx.x;
    const int d     = chunk * 128 + t;
    const size_t rowbase = (size_t)b * LL + (size_t)seg * SEGL;

    float a[DSTATE];
#pragma unroll
    for (int s = 0; s < DSTATE; s++) a[s] = -__expf(A_log[d * DSTATE + s]);

    bool fast = true;
#pragma unroll
    for (int s = 1; s < DSTATE; s++) {
        const float ideal = a[0] * (float)(s + 1);
        if (fabsf(a[s] - ideal) > 1e-4f * fabsf(ideal)) fast = false;
    }
    fast = __syncthreads_and(fast ? 1 : 0);

    const float LOG2E = 1.44269504088896f;
    const float c1 = a[0] * LOG2E;
    float cs[DSTATE];
#pragma unroll
    for (int s = 0; s < DSTATE; s++) cs[s] = a[s] * LOG2E;
    const float dpv = (PHASE == 1) ? Dp[d] : 0.f;

    float h[DSTATE];
    float Ecum[DSTATE];
    const size_t stOff = ((size_t)(b * NSEG + seg) * DSTATE) * DIN + d;
    if (PHASE == 0) {
#pragma unroll
        for (int s = 0; s < DSTATE; s++) { h[s] = 0.f; Ecum[s] = 1.f; }
    } else {
#pragma unroll
        for (int s = 0; s < DSTATE; s++) h[s] = H0[stOff + (size_t)s * DIN];
    }

    const int role = t >> 5;
    const int lane = t & 31;

    auto issue = [&](int tt) {
        const int slot = tt & (SSTAGE - 1);
        const size_t row = rowbase + tt;
        const float* gp = nullptr;
        int soff = 0;
        bool active = true;
        if (role == 0)      { gp = dt + row * DIN + chunk * 128 + lane * 4;             soff = lane * 4; }
        else if (role == 1) { gp = xc + row * DIN + chunk * 128 + lane * 4;             soff = 128 + lane * 4; }
        else if (role == 2) { active = (PHASE == 1);   // z only needed in phase C
                              gp = xz + row * (2 * DIN) + DIN + chunk * 128 + lane * 4; soff = 256 + lane * 4; }
        else                { active = (lane < 8);
                              gp = xdbl + row * XPROJ + DTRANK + lane * 4;              soff = 384 + lane * 4; }
        if (active)
            cp16((uint32_t)__cvta_generic_to_shared(&sbuf[slot][soff]), gp);
        cp_commit();
    };

    for (int tt = 0; tt < SSTAGE - 1; tt++) issue(tt);

    auto run = [&](auto fastc) {
        constexpr bool FAST = decltype(fastc)::value;
        for (int tt = 0; tt < SEGL; tt++) {
            CP_WAIT(SSTAGE - 2);
            __syncthreads();
            if (tt + SSTAGE - 1 < SEGL) issue(tt + SSTAGE - 1);

            const int slot = tt & (SSTAGE - 1);
            const float u  = sbuf[slot][t];
            const float xv = sbuf[slot][128 + t];
            float Bv[DSTATE], Cv[DSTATE];
#pragma unroll
            for (int q = 0; q < 4; q++) {
                float4 vb = *(const float4*)&sbuf[slot][384 + q * 4];
                Bv[q*4+0] = vb.x; Bv[q*4+1] = vb.y; Bv[q*4+2] = vb.z; Bv[q*4+3] = vb.w;
                if (PHASE == 1) {
                    float4 vc = *(const float4*)&sbuf[slot][400 + q * 4];
                    Cv[q*4+0] = vc.x; Cv[q*4+1] = vc.y; Cv[q*4+2] = vc.z; Cv[q*4+3] = vc.w;
                }
            }

            float e[DSTATE];
            if (FAST) {
                const float r = exp2f(u * c1);
                e[0]  = r;
                e[1]  = r * r;
                e[3]  = e[1] * e[1];
                e[7]  = e[3] * e[3];
                e[15] = e[7] * e[7];
                e[2]  = e[1] * r;
                e[4]  = e[3] * r;     e[5]  = e[3] * e[1];  e[6]  = e[3] * e[2];
                e[8]  = e[7] * r;     e[9]  = e[7] * e[1];  e[10] = e[7] * e[2];
                e[11] = e[7] * e[3];  e[12] = e[7] * e[4];  e[13] = e[7] * e[5];
                e[14] = e[7] * e[6];
            } else {
#pragma unroll
                for (int s = 0; s < DSTATE; s++) e[s] = exp2f(u * cs[s]);
            }

            const float ux = u * xv;
            if (PHASE == 0) {
#pragma unroll
                for (int s = 0; s < DSTATE; s++) {
                    h[s]    = fmaf(e[s], h[s], ux * Bv[s]);
                    Ecum[s] = Ecum[s] * e[s];
                }
            } else {
                const float zv = sbuf[slot][256 + t];
                float y0 = 0.f, y1 = 0.f, y2 = 0.f, y3 = 0.f;
#pragma unroll
                for (int s = 0; s < DSTATE; s += 4) {
                    h[s+0] = fmaf(e[s+0], h[s+0], ux * Bv[s+0]);
                    h[s+1] = fmaf(e[s+1], h[s+1], ux * Bv[s+1]);
                    h[s+2] = fmaf(e[s+2], h[s+2], ux * Bv[s+2]);
                    h[s+3] = fmaf(e[s+3], h[s+3], ux * Bv[s+3]);
                    y0 = fmaf(h[s+0], Cv[s+0], y0);
                    y1 = fmaf(h[s+1], Cv[s+1], y1);
                    y2 = fmaf(h[s+2], Cv[s+2], y2);
                    y3 = fmaf(h[s+3], Cv[s+3], y3);
                }
                float yt = (y0 + y1) + (y2 + y3);
                yt = fmaf(xv, dpv, yt);
                const float sig = 1.f / (1.f + __expf(-zv));
                const float out = yt * (zv * sig);
                __nv_bfloat16 oh, ol;
                split_bf16(out, oh, ol);
                const size_t oidx = (rowbase + tt) * DIN + chunk * 128 + t;
                yh[oidx] = oh;
                yl[oidx] = ol;
            }
        }
    };

    if (fast) run(std::true_type{});
    else      run(std::false_type{});

    if (PHASE == 0) {
#pragma unroll
        for (int s = 0; s < DSTATE; s++) {
            Hseg[stOff + (size_t)s * DIN] = h[s];
            Eseg[stOff + (size_t)s * DIN] = Ecum[s];
        }
    }
}

// sequential composition across segments: H0[b][seg] = state entering segment
__global__ void scan_combine(const float* __restrict__ Hseg,
                             const float* __restrict__ Eseg,
                             float* __restrict__ H0)
{
    const int idx = blockIdx.x * blockDim.x + threadIdx.x;
    if (idx >= BB * DIN) return;
    const int b = idx / DIN, d = idx % DIN;
    float h[DSTATE];
#pragma unroll
    for (int s = 0; s < DSTATE; s++) h[s] = 0.f;
    for (int seg = 0; seg < NSEG; seg++) {
        const size_t o = ((size_t)(b * NSEG + seg) * DSTATE) * DIN + d;
#pragma unroll
        for (int s = 0; s < DSTATE; s++) {
            const size_t os = o + (size_t)s * DIN;
            H0[os] = h[s];
            h[s] = fmaf(Eseg[os], h[s], Hseg[os]);
        }
    }
}

// ------------------------------------------------------------------- launch
extern "C" void kernel_launch(void* const* d_in, const int* in_sizes, int n_in,
                              void* d_out, int out_size)
{
    const float* x      = (const float*)d_in[0];
    const int*   mask   = (const int*)  d_in[1];
    const float* ln_g   = (const float*)d_in[2];
    const float* ln_b   = (const float*)d_in[3];
    const float* W_in   = (const float*)d_in[4];
    const float* conv_w = (const float*)d_in[5];
    const float* conv_b = (const float*)d_in[6];
    const float* W_xp   = (const float*)d_in[7];
    const float* W_dt   = (const float*)d_in[8];
    const float* b_dt   = (const float*)d_in[9];
    const float* A_log  = (const float*)d_in[10];
    const float* Dp     = (const float*)d_in[11];
    const float* W_out  = (const float*)d_in[12];
    float* out = (float*)d_out;

    static float *p_xz = nullptr, *p_xc, *p_xdbl, *p_dt, *p_Hs, *p_Es, *p_H0;
    static __nv_bfloat16 *p_axh, *p_axl, *p_wih, *p_wil, *p_ayh, *p_ayl, *p_woh, *p_wol;
    static __nv_bfloat16 *p_xch, *p_xcl, *p_wxh, *p_wxl, *p_xdh, *p_xdl, *p_wdh, *p_wdl;
    if (!p_xz) {
        cudaGetSymbolAddress((void**)&p_xz,   g_xz);
        cudaGetSymbolAddress((void**)&p_xc,   g_xc);
        cudaGetSymbolAddress((void**)&p_xdbl, g_xdbl);
        cudaGetSymbolAddress((void**)&p_dt,   g_dt);
        cudaGetSymbolAddress((void**)&p_Hs,   g_Hseg);
        cudaGetSymbolAddress((void**)&p_Es,   g_Eseg);
        cudaGetSymbolAddress((void**)&p_H0,   g_H0);
        cudaGetSymbolAddress((void**)&p_axh,  g_axh);
        cudaGetSymbolAddress((void**)&p_axl,  g_axl);
        cudaGetSymbolAddress((void**)&p_wih,  g_wih);
        cudaGetSymbolAddress((void**)&p_wil,  g_wil);
        cudaGetSymbolAddress((void**)&p_ayh,  g_ayh);
        cudaGetSymbolAddress((void**)&p_ayl,  g_ayl);
        cudaGetSymbolAddress((void**)&p_woh,  g_woh);
        cudaGetSymbolAddress((void**)&p_wol,  g_wol);
        cudaGetSymbolAddress((void**)&p_xch,  g_xch);
        cudaGetSymbolAddress((void**)&p_xcl,  g_xcl);
        cudaGetSymbolAddress((void**)&p_wxh,  g_wxh);
        cudaGetSymbolAddress((void**)&p_wxl,  g_wxl);
        cudaGetSymbolAddress((void**)&p_xdh,  g_xdh);
        cudaGetSymbolAddress((void**)&p_xdl,  g_xdl);
        cudaGetSymbolAddress((void**)&p_wdh,  g_wdh);
        cudaGetSymbolAddress((void**)&p_wdl,  g_wdl);
        cudaFuncSetAttribute(tgemm<0>, cudaFuncAttributeMaxDynamicSharedMemorySize, MM_SMEM);
        cudaFuncSetAttribute(tgemm<1>, cudaFuncAttributeMaxDynamicSharedMemorySize, MM_SMEM);
        cudaFuncSetAttribute(tgemm<2>, cudaFuncAttributeMaxDynamicSharedMemorySize, MM_SMEM);
        cudaFuncSetAttribute(tgemm<3>, cudaFuncAttributeMaxDynamicSharedMemorySize, MM_SMEM);
    }

    // 1. LayerNorm + mask + bf16 split pack
    ln_kernel<<<NROWS, 256>>>(x, mask, ln_g, ln_b, p_axh, p_axl);

    // 2. pack weights
    {
        long long nW = (long long)(2 * DIN) * DIMM / 8;
        pack_split<<<(unsigned)((nW + 255) / 256), 256>>>(W_in, (uint4*)p_wih, (uint4*)p_wil, nW);
        long long nO = (long long)DIMM * DIN / 8;
        pack_split<<<(unsigned)((nO + 255) / 256), 256>>>(W_out, (uint4*)p_woh, (uint4*)p_wol, nO);
        pack_pad<<<(128 * DIN + 255) / 256, 256>>>(W_xp, p_wxh, p_wxl, XPROJ, DIN, 128, DIN);
        pack_pad<<<(DIN * DTPADK + 255) / 256, 256>>>(W_dt, p_wdh, p_wdl, DIN, DTRANK, DIN, DTPADK);
    }

    // 3. in_proj: xz = xn @ W_in^T   (16384 x 3072, K=768)
    {
        dim3 g((2 * DIN) / 128, NROWS / 128);
        tgemm<0><<<g, 256, MM_SMEM>>>(p_axh, p_axl, p_wih, p_wil,
                                      p_xz, 2 * DIN, DIMM, 2 * DIN,
                                      nullptr, nullptr, nullptr, nullptr, nullptr);
    }

    // 4. depthwise causal conv + SiLU (+ bf16 split of xc)
    {
        const long long n = (long long)NROWS * DIN;
        conv_silu<<<(unsigned)((n + 255) / 256), 256>>>(p_xz, conv_w, conv_b,
                                                        p_xc, p_xch, p_xcl);
    }

    // 5. x_proj on tensor: xdbl = xc @ W_xp^T (N pad 80->128, K=1536)
    {
        dim3 g(1, NROWS / 128);
        tgemm<3><<<g, 256, MM_SMEM>>>(p_xch, p_xcl, p_wxh, p_wxl,
                                      p_xdbl, XPROJ, DIN, XPROJ,
                                      nullptr, nullptr, nullptr, p_xdh, p_xdl);
    }

    // 6. dt_proj on tensor + softplus (K padded 48->64)
    {
        dim3 g(DIN / 128, NROWS / 128);
        tgemm<1><<<g, 256, MM_SMEM>>>(p_xdh, p_xdl, p_wdh, p_wdl,
                                      p_dt, DIN, DTPADK, DIN,
                                      b_dt, nullptr, nullptr, nullptr, nullptr);
    }

    // 7. segmented selective scan (A: local states, B: compose, C: emit y)
    {
        const int nblk = BB * (DIN / 128) * NSEG;   // 768
        scan_seg<0><<<nblk, 128>>>(p_dt, p_xc, p_xz, p_xdbl, A_log, Dp,
                                   p_Hs, p_Es, nullptr, nullptr, nullptr);
        scan_combine<<<(BB * DIN + 255) / 256, 256>>>(p_Hs, p_Es, p_H0);
        scan_seg<1><<<nblk, 128>>>(p_dt, p_xc, p_xz, p_xdbl, A_log, Dp,
                                   nullptr, nullptr, p_H0, p_ayh, p_ayl);
    }

    // 8. out_proj + residual + mask
    {
        dim3 g(DIMM / 128, NROWS / 128);
        tgemm<2><<<g, 256, MM_SMEM>>>(p_ayh, p_ayl, p_woh, p_wol,
                                      out, DIMM, DIN, DIMM,
                                      nullptr, x, mask, nullptr, nullptr);
    }
}

// round 10
// speedup vs baseline: 1.4550x; 1.0406x over previous
#include <cuda_runtime.h>
#include <cuda_bf16.h>
#include <cstdint>
#include <type_traits>

#define BB      8
#define LL      2048
#define DIMM    768
#define DIN     1536
#define DSTATE  16
#define DTRANK  48
#define NROWS   (BB * LL)              // 16384
#define XPROJ   (DTRANK + 2 * DSTATE)  // 80
#define DTPADK  64                     // dt_proj K padded 48 -> 64
#define NSEG    8                      // scan segments
#define SEGL    (LL / NSEG)            // 256 steps per segment

// ---------------- scratch (static device globals; no allocation allowed) ---
__device__ float g_xz  [(size_t)NROWS * 2 * DIN];
__device__ float g_xc  [(size_t)NROWS * DIN];
__device__ float g_xdbl[(size_t)NROWS * XPROJ];
__device__ float g_dt  [(size_t)NROWS * DIN];
// segmented-scan state buffers: layout [b][seg][s][DIN]
__device__ float g_Hseg[(size_t)BB * NSEG * DSTATE * DIN];
__device__ float g_Eseg[(size_t)BB * NSEG * DSTATE * DIN];
__device__ float g_H0  [(size_t)BB * NSEG * DSTATE * DIN];

// bf16 hi/lo split operands (plain row-major)
__device__ __align__(128) __nv_bfloat16 g_axh[(size_t)NROWS * DIMM];
__device__ __align__(128) __nv_bfloat16 g_axl[(size_t)NROWS * DIMM];
__device__ __align__(128) __nv_bfloat16 g_wih[(size_t)(2*DIN) * DIMM];
__device__ __align__(128) __nv_bfloat16 g_wil[(size_t)(2*DIN) * DIMM];
__device__ __align__(128) __nv_bfloat16 g_ayh[(size_t)NROWS * DIN];
__device__ __align__(128) __nv_bfloat16 g_ayl[(size_t)NROWS * DIN];
__device__ __align__(128) __nv_bfloat16 g_woh[(size_t)DIMM * DIN];
__device__ __align__(128) __nv_bfloat16 g_wol[(size_t)DIMM * DIN];
// xc split (A of x_proj)
__device__ __align__(128) __nv_bfloat16 g_xch[(size_t)NROWS * DIN];
__device__ __align__(128) __nv_bfloat16 g_xcl[(size_t)NROWS * DIN];
// W_xp padded to 128 rows (B of x_proj)
__device__ __align__(128) __nv_bfloat16 g_wxh[(size_t)128 * DIN];
__device__ __align__(128) __nv_bfloat16 g_wxl[(size_t)128 * DIN];
// dt input split, K padded to 64 (A of dt_proj)
__device__ __align__(128) __nv_bfloat16 g_xdh[(size_t)NROWS * DTPADK];
__device__ __align__(128) __nv_bfloat16 g_xdl[(size_t)NROWS * DTPADK];
// W_dt padded K 48->64 (B of dt_proj)
__device__ __align__(128) __nv_bfloat16 g_wdh[(size_t)DIN * DTPADK];
__device__ __align__(128) __nv_bfloat16 g_wdl[(size_t)DIN * DTPADK];

// ======================== PTX helpers ============================
__device__ __forceinline__ uint32_t smem_u32(const void* p) {
    uint32_t a;
    asm("{ .reg .u64 t; cvta.to.shared.u64 t, %1; cvt.u32.u64 %0, t; }"
        : "=r"(a) : "l"(p));
    return a;
}
__device__ __forceinline__ void cp16(uint32_t dst, const void* src) {
    asm volatile("cp.async.cg.shared.global [%0], [%1], 16;" :: "r"(dst), "l"(src));
}
__device__ __forceinline__ void cp_commit() {
    asm volatile("cp.async.commit_group;" ::: "memory");
}
#define CP_WAIT(n) asm volatile("cp.async.wait_group %0;" :: "n"(n) : "memory")

#define LDSM4(r0, r1, r2, r3, addr) \
    asm volatile("ldmatrix.sync.aligned.m8n8.x4.shared.b16 {%0,%1,%2,%3}, [%4];" \
                 : "=r"(r0), "=r"(r1), "=r"(r2), "=r"(r3) : "r"(addr))
#define LDSM2(r0, r1, addr) \
    asm volatile("ldmatrix.sync.aligned.m8n8.x2.shared.b16 {%0,%1}, [%2];" \
                 : "=r"(r0), "=r"(r1) : "r"(addr))
#define MMA16816(d, a, b) \
    asm volatile("mma.sync.aligned.m16n8k16.row.col.f32.bf16.bf16.f32 " \
                 "{%0,%1,%2,%3},{%4,%5,%6,%7},{%8,%9},{%0,%1,%2,%3};" \
                 : "+f"((d)[0]), "+f"((d)[1]), "+f"((d)[2]), "+f"((d)[3]) \
                 : "r"((a)[0]), "r"((a)[1]), "r"((a)[2]), "r"((a)[3]), \
                   "r"((b)[0]), "r"((b)[1]))

__device__ __forceinline__ void split_bf16(float f, __nv_bfloat16& h, __nv_bfloat16& l) {
    h = __float2bfloat16(f);
    l = __float2bfloat16(f - __bfloat162float(h));
}
__device__ __forceinline__ float softplusf(float v) {
    return (v > 20.f) ? v : log1pf(__expf(v));
}

// =========================== pack / split kernels ==========================
__global__ void pack_split(const float* __restrict__ in,
                           uint4* __restrict__ hi, uint4* __restrict__ lo,
                           long long total8)
{
    const long long idx = (long long)blockIdx.x * blockDim.x + threadIdx.x;
    if (idx >= total8) return;
    const float* p = in + idx * 8;
    uint32_t uh[4], ul[4];
#pragma unroll
    for (int j = 0; j < 4; j++) {
        __nv_bfloat16 h0, h1, l0, l1;
        split_bf16(p[2*j],     h0, l0);
        split_bf16(p[2*j + 1], h1, l1);
        uh[j] = (uint32_t)__bfloat16_as_ushort(h0) | ((uint32_t)__bfloat16_as_ushort(h1) << 16);
        ul[j] = (uint32_t)__bfloat16_as_ushort(l0) | ((uint32_t)__bfloat16_as_ushort(l1) << 16);
    }
    hi[idx] = make_uint4(uh[0], uh[1], uh[2], uh[3]);
    lo[idx] = make_uint4(ul[0], ul[1], ul[2], ul[3]);
}

// pad-aware pack: in [R,K] -> out [Rp,Kp] (zeros outside). Small matrices only.
__global__ void pack_pad(const float* __restrict__ in,
                         __nv_bfloat16* __restrict__ hi, __nv_bfloat16* __restrict__ lo,
                         int R, int K, int Rp, int Kp)
{
    const int idx = blockIdx.x * blockDim.x + threadIdx.x;
    if (idx >= Rp * Kp) return;
    const int r = idx / Kp, k = idx % Kp;
    float v = (r < R && k < K) ? in[(size_t)r * K + k] : 0.f;
    __nv_bfloat16 h, l;
    split_bf16(v, h, l);
    hi[idx] = h;
    lo[idx] = l;
}

// ================== mma.sync bf16 3-pass split TN GEMM =====================
// ROUND 10: 2-stage double buffer with CORRECT ordering:
//   issue load(c+1) first, CP_WAIT(1) -> chunk c landed, compute, then a
//   trailing __syncthreads so next iteration's load can't overwrite the slot
//   while peers still read it.  2 CTAs/SM via launch_bounds(256,2) + 80KB smem.
// EPI 0: store fp32.           EPI 1: softplus(acc + bias[col]) -> fp32.
// EPI 2: mask[m]*(X+acc).      EPI 3: fp32 (col<Ntot) + bf16 hi/lo of
//                                      cols<48 (zeros 48..63) into aux (ld 64).
#define MM_STG_ROW   40
#define MM_BUF       (128 * 80)
#define MM_STAGE     (4 * MM_BUF)       // 40960 B
#define MM_NSTG      2
#define MM_SMEM      (MM_NSTG * MM_STAGE)   // 81920 B -> 2 CTAs/SM

template<int EPI>
__global__ __launch_bounds__(256, 2)
void tgemm(const __nv_bfloat16* __restrict__ Ah, const __nv_bfloat16* __restrict__ Al,
           const __nv_bfloat16* __restrict__ Bh, const __nv_bfloat16* __restrict__ Bl,
           float* __restrict__ C, int ldc, int K, int Ntot,
           const float* __restrict__ bias,
           const float* __restrict__ X, const int* __restrict__ mask,
           __nv_bfloat16* __restrict__ auxh, __nv_bfloat16* __restrict__ auxl)
{
    extern __shared__ char smem[];
    const uint32_t sBase = smem_u32(smem);

    const int tid  = threadIdx.x;
    const int wid  = tid >> 5;
    const int lane = tid & 31;
    const int wm   = wid & 1;
    const int wn   = wid >> 1;
    const int m0   = blockIdx.y * 128;
    const int n0   = blockIdx.x * 128;
    const int NK   = K / 32;

    auto load_stage = [&](int c, int slot) {
        const uint32_t sb = sBase + slot * MM_STAGE;
        const int k0 = c * 32;
#pragma unroll
        for (int h = 0; h < 2; h++) {
            const int ch  = tid + h * 256;
            const int row = ch >> 2;
            const int kc  = ch & 3;
            const uint32_t doff = row * 80 + kc * 16;
            const size_t goffA = (size_t)(m0 + row) * K + k0 + kc * 8;
            const size_t goffB = (size_t)(n0 + row) * K + k0 + kc * 8;
            cp16(sb + doff,               Ah + goffA);
            cp16(sb + MM_BUF + doff,      Al + goffA);
            cp16(sb + 2*MM_BUF + doff,    Bh + goffB);
            cp16(sb + 3*MM_BUF + doff,    Bl + goffB);
        }
    };

    float acc[4][4][4];
#pragma unroll
    for (int i = 0; i < 4; i++)
#pragma unroll
        for (int j = 0; j < 4; j++)
#pragma unroll
            for (int r = 0; r < 4; r++) acc[i][j][r] = 0.f;

    load_stage(0, 0); cp_commit();

    const int aRowB = wm * 64 + ((lane >> 3) & 1) * 8 + (lane & 7);
    const int aKB   = (lane >> 4) * 8;
    const int bRowB = wn * 32 + (lane & 7);
    const int bKB   = ((lane >> 3) & 1) * 8;

    for (int c = 0; c < NK; c++) {
        if (c + 1 < NK) load_stage(c + 1, (c + 1) & 1);
        cp_commit();
        CP_WAIT(1);             // chunk c's group complete
        __syncthreads();
        const uint32_t sb = sBase + (c & 1) * MM_STAGE;

#pragma unroll
        for (int kk = 0; kk < 2; kk++) {
            uint32_t ah[4][4], al[4][4], bh[4][2], bl[4][2];
#pragma unroll
            for (int mi = 0; mi < 4; mi++) {
                const uint32_t ad = sb + ((aRowB + mi * 16) * MM_STG_ROW
                                          + aKB + kk * 16) * 2;
                LDSM4(ah[mi][0], ah[mi][1], ah[mi][2], ah[mi][3], ad);
                LDSM4(al[mi][0], al[mi][1], al[mi][2], al[mi][3], ad + MM_BUF);
            }
#pragma unroll
            for (int ni = 0; ni < 4; ni++) {
                const uint32_t bd = sb + 2*MM_BUF + ((bRowB + ni * 8) * MM_STG_ROW
                                                     + bKB + kk * 16) * 2;
                LDSM2(bh[ni][0], bh[ni][1], bd);
                LDSM2(bl[ni][0], bl[ni][1], bd + MM_BUF);
            }
#pragma unroll
            for (int mi = 0; mi < 4; mi++)
#pragma unroll
                for (int ni = 0; ni < 4; ni++) {
                    MMA16816(acc[mi][ni], ah[mi], bh[ni]);
                    MMA16816(acc[mi][ni], ah[mi], bl[ni]);
                    MMA16816(acc[mi][ni], al[mi], bh[ni]);
                }
        }
        __syncthreads();        // protect slot c&1 before next iter's load
    }

    const int rq = lane >> 2;
    const int cq = (lane & 3) * 2;
#pragma unroll
    for (int mi = 0; mi < 4; mi++) {
        const int r0 = m0 + wm * 64 + mi * 16 + rq;
        const int r1 = r0 + 8;
        float mf0 = 1.f, mf1 = 1.f;
        if (EPI == 2) { mf0 = (float)mask[r0]; mf1 = (float)mask[r1]; }
#pragma unroll
        for (int ni = 0; ni < 4; ni++) {
            const int cc = n0 + wn * 32 + ni * 8 + cq;
            float v0 = acc[mi][ni][0], v1 = acc[mi][ni][1];
            float v2 = acc[mi][ni][2], v3 = acc[mi][ni][3];
            if (EPI == 1) {
                const float b0 = bias[cc], b1 = bias[cc + 1];
                v0 = softplusf(v0 + b0); v1 = softplusf(v1 + b1);
                v2 = softplusf(v2 + b0); v3 = softplusf(v3 + b1);
            } else if (EPI == 2) {
                const float* x0 = X + (size_t)r0 * ldc + cc;
                const float* x1 = X + (size_t)r1 * ldc + cc;
                v0 = mf0 * (x0[0] + v0); v1 = mf0 * (x0[1] + v1);
                v2 = mf1 * (x1[0] + v2); v3 = mf1 * (x1[1] + v3);
            }
            if (EPI != 3 || cc + 1 < Ntot) {
                *(float2*)(C + (size_t)r0 * ldc + cc) = make_float2(v0, v1);
                *(float2*)(C + (size_t)r1 * ldc + cc) = make_float2(v2, v3);
            }
            if (EPI == 3) {
#pragma unroll
                for (int j = 0; j < 2; j++) {
                    const int col = cc + j;
                    if (col < DTPADK) {
                        const float a0 = (col < DTRANK) ? ((j == 0) ? v0 : v1) : 0.f;
                        const float a1 = (col < DTRANK) ? ((j == 0) ? v2 : v3) : 0.f;
                        __nv_bfloat16 h, l;
                        split_bf16(a0, h, l);
                        auxh[(size_t)r0 * DTPADK + col] = h;
                        auxl[(size_t)r0 * DTPADK + col] = l;
                        split_bf16(a1, h, l);
                        auxh[(size_t)r1 * DTPADK + col] = h;
                        auxl[(size_t)r1 * DTPADK + col] = l;
                    }
                }
            }
        }
    }
}

// --------------------------- LayerNorm + fused bf16 split pack -------------
__global__ void ln_kernel(const float* __restrict__ x,
                          const int*   __restrict__ mask,
                          const float* __restrict__ g,
                          const float* __restrict__ b,
                          __nv_bfloat16* __restrict__ xh,
                          __nv_bfloat16* __restrict__ xl)
{
    const int row = blockIdx.x;
    const int t   = threadIdx.x;
    const float* xr = x + (size_t)row * DIMM;

    float v[3];
    float s = 0.f, s2 = 0.f;
#pragma unroll
    for (int j = 0; j < 3; j++) {
        v[j] = xr[t + j * 256];
        s  += v[j];
        s2 += v[j] * v[j];
    }
    __shared__ float red[2][8];
#pragma unroll
    for (int o = 16; o > 0; o >>= 1) {
        s  += __shfl_xor_sync(0xffffffffu, s,  o);
        s2 += __shfl_xor_sync(0xffffffffu, s2, o);
    }
    if ((t & 31) == 0) { red[0][t >> 5] = s; red[1][t >> 5] = s2; }
    __syncthreads();
    float ts = 0.f, ts2 = 0.f;
#pragma unroll
    for (int j = 0; j < 8; j++) { ts += red[0][j]; ts2 += red[1][j]; }

    const float mu   = ts * (1.0f / DIMM);
    const float var  = ts2 * (1.0f / DIMM) - mu * mu;
    const float rstd = rsqrtf(var + 1e-5f);
    const float mf   = (float)mask[row];

#pragma unroll
    for (int j = 0; j < 3; j++) {
        const int c = t + j * 256;
        const float o = ((v[j] - mu) * rstd * g[c] + b[c]) * mf;
        __nv_bfloat16 h, l;
        split_bf16(o, h, l);
        xh[(size_t)row * DIMM + c] = h;
        xl[(size_t)row * DIMM + c] = l;
    }
}

// --------------- depthwise causal conv4 + SiLU + bf16 split ----------------
__global__ void conv_silu(const float* __restrict__ xz,
                          const float* __restrict__ w,
                          const float* __restrict__ bias,
                          float* __restrict__ xc,
                          __nv_bfloat16* __restrict__ xch,
                          __nv_bfloat16* __restrict__ xcl)
{
    const long long idx = (long long)blockIdx.x * blockDim.x + threadIdx.x;
    if (idx >= (long long)NROWS * DIN) return;
    const int d = (int)(idx % DIN);
    const int i = (int)(idx / DIN);
    const int l = i % LL;

    float s = bias[d];
    const float* wp = w + d * 4;
#pragma unroll
    for (int j = 0; j < 4; j++) {
        const int ll = l - 3 + j;
        if (ll >= 0)
            s = fmaf(wp[j], xz[(size_t)(i - 3 + j) * (2 * DIN) + d], s);
    }
    const float sig = 1.f / (1.f + __expf(-s));
    const float o = s * sig;
    xc[idx] = o;
    __nv_bfloat16 h, l2;
    split_bf16(o, h, l2);
    xch[idx] = h;
    xcl[idx] = l2;
}

// ======================= segmented selective scan ==========================
#define SSTAGE 8
#define STAGEF 416   // 128 dt + 128 xc + 128 z + 32 bc

template<int PHASE>
__global__ __launch_bounds__(128)
void scan_seg(const float* __restrict__ dt,
              const float* __restrict__ xc,
              const float* __restrict__ xz,
              const float* __restrict__ xdbl,
              const float* __restrict__ A_log,
              const float* __restrict__ Dp,
              float* __restrict__ Hseg,
              float* __restrict__ Eseg,
              const float* __restrict__ H0,
              __nv_bfloat16* __restrict__ yh,
              __nv_bfloat16* __restrict__ yl)
{
    __shared__ float sbuf[SSTAGE][STAGEF];

    const int bx    = blockIdx.x;
    const int b     = bx / ((DIN / 128) * NSEG);
    const int rem   = bx % ((DIN / 128) * NSEG);
    const int chunk = rem / NSEG;
    const int seg   = rem % NSEG;
    const int t     = threadIdx.x;
    const int d     = chunk * 128 + t;
    const size_t rowbase = (size_t)b * LL + (size_t)seg * SEGL;

    float a[DSTATE];
#pragma unroll
    for (int s = 0; s < DSTATE; s++) a[s] = -__expf(A_log[d * DSTATE + s]);

    bool fast = true;
#pragma unroll
    for (int s = 1; s < DSTATE; s++) {
        const float ideal = a[0] * (float)(s + 1);
        if (fabsf(a[s] - ideal) > 1e-4f * fabsf(ideal)) fast = false;
    }
    fast = __syncthreads_and(fast ? 1 : 0);

    const float LOG2E = 1.44269504088896f;
    const float c1 = a[0] * LOG2E;
    float cs[DSTATE];
#pragma unroll
    for (int s = 0; s < DSTATE; s++) cs[s] = a[s] * LOG2E;
    const float dpv = (PHASE == 1) ? Dp[d] : 0.f;

    float h[DSTATE];
    float Ecum[DSTATE];
    const size_t stOff = ((size_t)(b * NSEG + seg) * DSTATE) * DIN + d;
    if (PHASE == 0) {
#pragma unroll
        for (int s = 0; s < DSTATE; s++) { h[s] = 0.f; Ecum[s] = 1.f; }
    } else {
#pragma unroll
        for (int s = 0; s < DSTATE; s++) h[s] = H0[stOff + (size_t)s * DIN];
    }

    const int role = t >> 5;
    const int lane = t & 31;

    auto issue = [&](int tt) {
        const int slot = tt & (SSTAGE - 1);
        const size_t row = rowbase + tt;
        const float* gp = nullptr;
        int soff = 0;
        bool active = true;
        if (role == 0)      { gp = dt + row * DIN + chunk * 128 + lane * 4;             soff = lane * 4; }
        else if (role == 1) { gp = xc + row * DIN + chunk * 128 + lane * 4;             soff = 128 + lane * 4; }
        else if (role == 2) { active = (PHASE == 1);
                              gp = xz + row * (2 * DIN) + DIN + chunk * 128 + lane * 4; soff = 256 + lane * 4; }
        else                { active = (lane < 8);
                              gp = xdbl + row * XPROJ + DTRANK + lane * 4;              soff = 384 + lane * 4; }
        if (active)
            cp16((uint32_t)__cvta_generic_to_shared(&sbuf[slot][soff]), gp);
        cp_commit();
    };

    for (int tt = 0; tt < SSTAGE - 1; tt++) issue(tt);

    auto run = [&](auto fastc) {
        constexpr bool FAST = decltype(fastc)::value;
        for (int tt = 0; tt < SEGL; tt++) {
            CP_WAIT(SSTAGE - 2);
            __syncthreads();
            if (tt + SSTAGE - 1 < SEGL) issue(tt + SSTAGE - 1);

            const int slot = tt & (SSTAGE - 1);
            const float u  = sbuf[slot][t];
            const float xv = sbuf[slot][128 + t];
            float Bv[DSTATE], Cv[DSTATE];
#pragma unroll
            for (int q = 0; q < 4; q++) {
                float4 vb = *(const float4*)&sbuf[slot][384 + q * 4];
                Bv[q*4+0] = vb.x; Bv[q*4+1] = vb.y; Bv[q*4+2] = vb.z; Bv[q*4+3] = vb.w;
                if (PHASE == 1) {
                    float4 vc = *(const float4*)&sbuf[slot][400 + q * 4];
                    Cv[q*4+0] = vc.x; Cv[q*4+1] = vc.y; Cv[q*4+2] = vc.z; Cv[q*4+3] = vc.w;
                }
            }

            float e[DSTATE];
            if (FAST) {
                const float r = exp2f(u * c1);
                e[0]  = r;
                e[1]  = r * r;
                e[3]  = e[1] * e[1];
                e[7]  = e[3] * e[3];
                e[15] = e[7] * e[7];
                e[2]  = e[1] * r;
                e[4]  = e[3] * r;     e[5]  = e[3] * e[1];  e[6]  = e[3] * e[2];
                e[8]  = e[7] * r;     e[9]  = e[7] * e[1];  e[10] = e[7] * e[2];
                e[11] = e[7] * e[3];  e[12] = e[7] * e[4];  e[13] = e[7] * e[5];
                e[14] = e[7] * e[6];
            } else {
#pragma unroll
                for (int s = 0; s < DSTATE; s++) e[s] = exp2f(u * cs[s]);
            }

            const float ux = u * xv;
            if (PHASE == 0) {
#pragma unroll
                for (int s = 0; s < DSTATE; s++) {
                    h[s]    = fmaf(e[s], h[s], ux * Bv[s]);
                    Ecum[s] = Ecum[s] * e[s];
                }
            } else {
                const float zv = sbuf[slot][256 + t];
                float y0 = 0.f, y1 = 0.f, y2 = 0.f, y3 = 0.f;
#pragma unroll
                for (int s = 0; s < DSTATE; s += 4) {
                    h[s+0] = fmaf(e[s+0], h[s+0], ux * Bv[s+0]);
                    h[s+1] = fmaf(e[s+1], h[s+1], ux * Bv[s+1]);
                    h[s+2] = fmaf(e[s+2], h[s+2], ux * Bv[s+2]);
                    h[s+3] = fmaf(e[s+3], h[s+3], ux * Bv[s+3]);
                    y0 = fmaf(h[s+0], Cv[s+0], y0);
                    y1 = fmaf(h[s+1], Cv[s+1], y1);
                    y2 = fmaf(h[s+2], Cv[s+2], y2);
                    y3 = fmaf(h[s+3], Cv[s+3], y3);
                }
                float yt = (y0 + y1) + (y2 + y3);
                yt = fmaf(xv, dpv, yt);
                const float sig = 1.f / (1.f + __expf(-zv));
                const float out = yt * (zv * sig);
                __nv_bfloat16 oh, ol;
                split_bf16(out, oh, ol);
                const size_t oidx = (rowbase + tt) * DIN + chunk * 128 + t;
                yh[oidx] = oh;
                yl[oidx] = ol;
            }
        }
    };

    if (fast) run(std::true_type{});
    else      run(std::false_type{});

    if (PHASE == 0) {
#pragma unroll
        for (int s = 0; s < DSTATE; s++) {
            Hseg[stOff + (size_t)s * DIN] = h[s];
            Eseg[stOff + (size_t)s * DIN] = Ecum[s];
        }
    }
}

// sequential composition across segments: H0[b][seg] = state entering segment
__global__ void scan_combine(const float* __restrict__ Hseg,
                             const float* __restrict__ Eseg,
                             float* __restrict__ H0)
{
    const int idx = blockIdx.x * blockDim.x + threadIdx.x;
    if (idx >= BB * DIN) return;
    const int b = idx / DIN, d = idx % DIN;
    float h[DSTATE];
#pragma unroll
    for (int s = 0; s < DSTATE; s++) h[s] = 0.f;
    for (int seg = 0; seg < NSEG; seg++) {
        const size_t o = ((size_t)(b * NSEG + seg) * DSTATE) * DIN + d;
#pragma unroll
        for (int s = 0; s < DSTATE; s++) {
            const size_t os = o + (size_t)s * DIN;
            H0[os] = h[s];
            h[s] = fmaf(Eseg[os], h[s], Hseg[os]);
        }
    }
}

// ------------------------------------------------------------------- launch
extern "C" void kernel_launch(void* const* d_in, const int* in_sizes, int n_in,
                              void* d_out, int out_size)
{
    const float* x      = (const float*)d_in[0];
    const int*   mask   = (const int*)  d_in[1];
    const float* ln_g   = (const float*)d_in[2];
    const float* ln_b   = (const float*)d_in[3];
    const float* W_in   = (const float*)d_in[4];
    const float* conv_w = (const float*)d_in[5];
    const float* conv_b = (const float*)d_in[6];
    const float* W_xp   = (const float*)d_in[7];
    const float* W_dt   = (const float*)d_in[8];
    const float* b_dt   = (const float*)d_in[9];
    const float* A_log  = (const float*)d_in[10];
    const float* Dp     = (const float*)d_in[11];
    const float* W_out  = (const float*)d_in[12];
    float* out = (float*)d_out;

    static float *p_xz = nullptr, *p_xc, *p_xdbl, *p_dt, *p_Hs, *p_Es, *p_H0;
    static __nv_bfloat16 *p_axh, *p_axl, *p_wih, *p_wil, *p_ayh, *p_ayl, *p_woh, *p_wol;
    static __nv_bfloat16 *p_xch, *p_xcl, *p_wxh, *p_wxl, *p_xdh, *p_xdl, *p_wdh, *p_wdl;
    if (!p_xz) {
        cudaGetSymbolAddress((void**)&p_xz,   g_xz);
        cudaGetSymbolAddress((void**)&p_xc,   g_xc);
        cudaGetSymbolAddress((void**)&p_xdbl, g_xdbl);
        cudaGetSymbolAddress((void**)&p_dt,   g_dt);
        cudaGetSymbolAddress((void**)&p_Hs,   g_Hseg);
        cudaGetSymbolAddress((void**)&p_Es,   g_Eseg);
        cudaGetSymbolAddress((void**)&p_H0,   g_H0);
        cudaGetSymbolAddress((void**)&p_axh,  g_axh);
        cudaGetSymbolAddress((void**)&p_axl,  g_axl);
        cudaGetSymbolAddress((void**)&p_wih,  g_wih);
        cudaGetSymbolAddress((void**)&p_wil,  g_wil);
        cudaGetSymbolAddress((void**)&p_ayh,  g_ayh);
        cudaGetSymbolAddress((void**)&p_ayl,  g_ayl);
        cudaGetSymbolAddress((void**)&p_woh,  g_woh);
        cudaGetSymbolAddress((void**)&p_wol,  g_wol);
        cudaGetSymbolAddress((void**)&p_xch,  g_xch);
        cudaGetSymbolAddress((void**)&p_xcl,  g_xcl);
        cudaGetSymbolAddress((void**)&p_wxh,  g_wxh);
        cudaGetSymbolAddress((void**)&p_wxl,  g_wxl);
        cudaGetSymbolAddress((void**)&p_xdh,  g_xdh);
        cudaGetSymbolAddress((void**)&p_xdl,  g_xdl);
        cudaGetSymbolAddress((void**)&p_wdh,  g_wdh);
        cudaGetSymbolAddress((void**)&p_wdl,  g_wdl);
        cudaFuncSetAttribute(tgemm<0>, cudaFuncAttributeMaxDynamicSharedMemorySize, MM_SMEM);
        cudaFuncSetAttribute(tgemm<1>, cudaFuncAttributeMaxDynamicSharedMemorySize, MM_SMEM);
        cudaFuncSetAttribute(tgemm<2>, cudaFuncAttributeMaxDynamicSharedMemorySize, MM_SMEM);
        cudaFuncSetAttribute(tgemm<3>, cudaFuncAttributeMaxDynamicSharedMemorySize, MM_SMEM);
    }

    // 1. LayerNorm + mask + bf16 split pack
    ln_kernel<<<NROWS, 256>>>(x, mask, ln_g, ln_b, p_axh, p_axl);

    // 2. pack weights
    {
        long long nW = (long long)(2 * DIN) * DIMM / 8;
        pack_split<<<(unsigned)((nW + 255) / 256), 256>>>(W_in, (uint4*)p_wih, (uint4*)p_wil, nW);
        long long nO = (long long)DIMM * DIN / 8;
        pack_split<<<(unsigned)((nO + 255) / 256), 256>>>(W_out, (uint4*)p_woh, (uint4*)p_wol, nO);
        pack_pad<<<(128 * DIN + 255) / 256, 256>>>(W_xp, p_wxh, p_wxl, XPROJ, DIN, 128, DIN);
        pack_pad<<<(DIN * DTPADK + 255) / 256, 256>>>(W_dt, p_wdh, p_wdl, DIN, DTRANK, DIN, DTPADK);
    }

    // 3. in_proj: xz = xn @ W_in^T   (16384 x 3072, K=768)
    {
        dim3 g((2 * DIN) / 128, NROWS / 128);
        tgemm<0><<<g, 256, MM_SMEM>>>(p_axh, p_axl, p_wih, p_wil,
                                      p_xz, 2 * DIN, DIMM, 2 * DIN,
                                      nullptr, nullptr, nullptr, nullptr, nullptr);
    }

    // 4. depthwise causal conv + SiLU (+ bf16 split of xc)
    {
        const long long n = (long long)NROWS * DIN;
        conv_silu<<<(unsigned)((n + 255) / 256), 256>>>(p_xz, conv_w, conv_b,
                                                        p_xc, p_xch, p_xcl);
    }

    // 5. x_proj on tensor: xdbl = xc @ W_xp^T (N pad 80->128, K=1536)
    {
        dim3 g(1, NROWS / 128);
        tgemm<3><<<g, 256, MM_SMEM>>>(p_xch, p_xcl, p_wxh, p_wxl,
                                      p_xdbl, XPROJ, DIN, XPROJ,
                                      nullptr, nullptr, nullptr, p_xdh, p_xdl);
    }

    // 6. dt_proj on tensor + softplus (K padded 48->64)
    {
        dim3 g(DIN / 128, NROWS / 128);
        tgemm<1><<<g, 256, MM_SMEM>>>(p_xdh, p_xdl, p_wdh, p_wdl,
                                      p_dt, DIN, DTPADK, DIN,
                                      b_dt, nullptr, nullptr, nullptr, nullptr);
    }

    // 7. segmented selective scan (A: local states, B: compose, C: emit y)
    {
        const int nblk = BB * (DIN / 128) * NSEG;   // 768
        scan_seg<0><<<nblk, 128>>>(p_dt, p_xc, p_xz, p_xdbl, A_log, Dp,
                                   p_Hs, p_Es, nullptr, nullptr, nullptr);
        scan_combine<<<(BB * DIN + 255) / 256, 256>>>(p_Hs, p_Es, p_H0);
        scan_seg<1><<<nblk, 128>>>(p_dt, p_xc, p_xz, p_xdbl, A_log, Dp,
                                   nullptr, nullptr, p_H0, p_ayh, p_ayl);
    }

    // 8. out_proj + residual + mask
    {
        dim3 g(DIMM / 128, NROWS / 128);
        tgemm<2><<<g, 256, MM_SMEM>>>(p_ayh, p_ayl, p_woh, p_wol,
                                      out, DIMM, DIN, DIMM,
                                      nullptr, x, mask, nullptr, nullptr);
    }
}

// round 11
// speedup vs baseline: 2.3831x; 1.6378x over previous
#include <cuda_runtime.h>
#include <cuda_fp16.h>
#include <cstdint>
#include <type_traits>

#define BB      8
#define LL      2048
#define DIMM    768
#define DIN     1536
#define DSTATE  16
#define DTRANK  48
#define NROWS   (BB * LL)              // 16384
#define XPROJ   (DTRANK + 2 * DSTATE)  // 80
#define DTPADK  64                     // dt_proj K padded 48 -> 64
#define NSEG    8                      // scan segments
#define SEGL    (LL / NSEG)            // 256 steps per segment

// ---------------- scratch (static device globals; no allocation allowed) ---
__device__ float g_xz  [(size_t)NROWS * 2 * DIN];
__device__ float g_xc  [(size_t)NROWS * DIN];
__device__ float g_xdbl[(size_t)NROWS * XPROJ];
__device__ float g_dt  [(size_t)NROWS * DIN];
// segmented-scan state buffers: layout [b][seg][s][DIN]
__device__ float g_Hseg[(size_t)BB * NSEG * DSTATE * DIN];
__device__ float g_Eseg[(size_t)BB * NSEG * DSTATE * DIN];
__device__ float g_H0  [(size_t)BB * NSEG * DSTATE * DIN];

// fp16 GEMM operands (plain row-major)
__device__ __align__(128) __half g_ax[(size_t)NROWS * DIMM];        // LN out
__device__ __align__(128) __half g_wi[(size_t)(2*DIN) * DIMM];      // W_in
__device__ __align__(128) __half g_ay[(size_t)NROWS * DIN];         // scan out
__device__ __align__(128) __half g_wo[(size_t)DIMM * DIN];          // W_out
__device__ __align__(128) __half g_xc16[(size_t)NROWS * DIN];       // conv out
__device__ __align__(128) __half g_wx[(size_t)128 * DIN];           // W_xp padded
__device__ __align__(128) __half g_xd[(size_t)NROWS * DTPADK];      // dt input
__device__ __align__(128) __half g_wd[(size_t)DIN * DTPADK];        // W_dt padded

// ======================== PTX helpers ============================
__device__ __forceinline__ uint32_t smem_u32(const void* p) {
    uint32_t a;
    asm("{ .reg .u64 t; cvta.to.shared.u64 t, %1; cvt.u32.u64 %0, t; }"
        : "=r"(a) : "l"(p));
    return a;
}
__device__ __forceinline__ void cp16(uint32_t dst, const void* src) {
    asm volatile("cp.async.cg.shared.global [%0], [%1], 16;" :: "r"(dst), "l"(src));
}
__device__ __forceinline__ void cp_commit() {
    asm volatile("cp.async.commit_group;" ::: "memory");
}
#define CP_WAIT(n) asm volatile("cp.async.wait_group %0;" :: "n"(n) : "memory")

#define LDSM4(r0, r1, r2, r3, addr) \
    asm volatile("ldmatrix.sync.aligned.m8n8.x4.shared.b16 {%0,%1,%2,%3}, [%4];" \
                 : "=r"(r0), "=r"(r1), "=r"(r2), "=r"(r3) : "r"(addr))
#define LDSM2(r0, r1, addr) \
    asm volatile("ldmatrix.sync.aligned.m8n8.x2.shared.b16 {%0,%1}, [%2];" \
                 : "=r"(r0), "=r"(r1) : "r"(addr))
#define MMA16816(d, a, b) \
    asm volatile("mma.sync.aligned.m16n8k16.row.col.f32.f16.f16.f32 " \
                 "{%0,%1,%2,%3},{%4,%5,%6,%7},{%8,%9},{%0,%1,%2,%3};" \
                 : "+f"((d)[0]), "+f"((d)[1]), "+f"((d)[2]), "+f"((d)[3]) \
                 : "r"((a)[0]), "r"((a)[1]), "r"((a)[2]), "r"((a)[3]), \
                   "r"((b)[0]), "r"((b)[1]))

__device__ __forceinline__ float softplusf(float v) {
    return (v > 20.f) ? v : log1pf(__expf(v));
}

// =========================== pack kernels ==========================
// fp32 [.] -> fp16, 8 values per thread (one uint4 out)
__global__ void pack_h(const float* __restrict__ in,
                       uint4* __restrict__ out, long long total8)
{
    const long long idx = (long long)blockIdx.x * blockDim.x + threadIdx.x;
    if (idx >= total8) return;
    const float* p = in + idx * 8;
    uint32_t u[4];
#pragma unroll
    for (int j = 0; j < 4; j++) {
        __half2 h2 = __floats2half2_rn(p[2*j], p[2*j + 1]);
        u[j] = *reinterpret_cast<uint32_t*>(&h2);
    }
    out[idx] = make_uint4(u[0], u[1], u[2], u[3]);
}

// pad-aware pack: in [R,K] -> out [Rp,Kp] (zeros outside). Small matrices only.
__global__ void pack_pad(const float* __restrict__ in,
                         __half* __restrict__ out,
                         int R, int K, int Rp, int Kp)
{
    const int idx = blockIdx.x * blockDim.x + threadIdx.x;
    if (idx >= Rp * Kp) return;
    const int r = idx / Kp, k = idx % Kp;
    float v = (r < R && k < K) ? in[(size_t)r * K + k] : 0.f;
    out[idx] = __float2half_rn(v);
}

// ================== mma.sync fp16 single-pass TN GEMM =====================
// round-10-proven 2-stage double buffer, 2 CTAs/SM; fp16 operands (1 MMA
// per fragment pair instead of the bf16 3-pass split).
// EPI 0: store fp32.           EPI 1: softplus(acc + bias[col]) -> fp32.
// EPI 2: mask[m]*(X+acc).      EPI 3: fp32 (col<Ntot) + fp16 of cols<48
//                                      (zeros 48..63) into aux (ld 64).
#define MM_STG_ROW   40
#define MM_BUF       (128 * 80)         // one operand buffer: 10240 B
#define MM_STAGE     (2 * MM_BUF)       // A, B: 20480 B
#define MM_NSTG      2
#define MM_SMEM      (MM_NSTG * MM_STAGE)   // 40960 B

template<int EPI>
__global__ __launch_bounds__(256, 2)
void tgemm(const __half* __restrict__ A, const __half* __restrict__ B,
           float* __restrict__ C, int ldc, int K, int Ntot,
           const float* __restrict__ bias,
           const float* __restrict__ X, const int* __restrict__ mask,
           __half* __restrict__ aux)
{
    extern __shared__ char smem[];
    const uint32_t sBase = smem_u32(smem);

    const int tid  = threadIdx.x;
    const int wid  = tid >> 5;
    const int lane = tid & 31;
    const int wm   = wid & 1;
    const int wn   = wid >> 1;
    const int m0   = blockIdx.y * 128;
    const int n0   = blockIdx.x * 128;
    const int NK   = K / 32;

    auto load_stage = [&](int c, int slot) {
        const uint32_t sb = sBase + slot * MM_STAGE;
        const int k0 = c * 32;
#pragma unroll
        for (int h = 0; h < 2; h++) {
            const int ch  = tid + h * 256;
            const int row = ch >> 2;
            const int kc  = ch & 3;
            const uint32_t doff = row * 80 + kc * 16;
            cp16(sb + doff,          A + (size_t)(m0 + row) * K + k0 + kc * 8);
            cp16(sb + MM_BUF + doff, B + (size_t)(n0 + row) * K + k0 + kc * 8);
        }
    };

    float acc[4][4][4];
#pragma unroll
    for (int i = 0; i < 4; i++)
#pragma unroll
        for (int j = 0; j < 4; j++)
#pragma unroll
            for (int r = 0; r < 4; r++) acc[i][j][r] = 0.f;

    load_stage(0, 0); cp_commit();

    const int aRowB = wm * 64 + ((lane >> 3) & 1) * 8 + (lane & 7);
    const int aKB   = (lane >> 4) * 8;
    const int bRowB = wn * 32 + (lane & 7);
    const int bKB   = ((lane >> 3) & 1) * 8;

    for (int c = 0; c < NK; c++) {
        if (c + 1 < NK) load_stage(c + 1, (c + 1) & 1);
        cp_commit();
        CP_WAIT(1);             // chunk c's group complete
        __syncthreads();
        const uint32_t sb = sBase + (c & 1) * MM_STAGE;

#pragma unroll
        for (int kk = 0; kk < 2; kk++) {
            uint32_t ah[4][4], bh[4][2];
#pragma unroll
            for (int mi = 0; mi < 4; mi++) {
                const uint32_t ad = sb + ((aRowB + mi * 16) * MM_STG_ROW
                                          + aKB + kk * 16) * 2;
                LDSM4(ah[mi][0], ah[mi][1], ah[mi][2], ah[mi][3], ad);
            }
#pragma unroll
            for (int ni = 0; ni < 4; ni++) {
                const uint32_t bd = sb + MM_BUF + ((bRowB + ni * 8) * MM_STG_ROW
                                                   + bKB + kk * 16) * 2;
                LDSM2(bh[ni][0], bh[ni][1], bd);
            }
#pragma unroll
            for (int mi = 0; mi < 4; mi++)
#pragma unroll
                for (int ni = 0; ni < 4; ni++)
                    MMA16816(acc[mi][ni], ah[mi], bh[ni]);
        }
        __syncthreads();        // protect slot c&1 before next iter's load
    }

    const int rq = lane >> 2;
    const int cq = (lane & 3) * 2;
#pragma unroll
    for (int mi = 0; mi < 4; mi++) {
        const int r0 = m0 + wm * 64 + mi * 16 + rq;
        const int r1 = r0 + 8;
        float mf0 = 1.f, mf1 = 1.f;
        if (EPI == 2) { mf0 = (float)mask[r0]; mf1 = (float)mask[r1]; }
#pragma unroll
        for (int ni = 0; ni < 4; ni++) {
            const int cc = n0 + wn * 32 + ni * 8 + cq;
            float v0 = acc[mi][ni][0], v1 = acc[mi][ni][1];
            float v2 = acc[mi][ni][2], v3 = acc[mi][ni][3];
            if (EPI == 1) {
                const float b0 = bias[cc], b1 = bias[cc + 1];
                v0 = softplusf(v0 + b0); v1 = softplusf(v1 + b1);
                v2 = softplusf(v2 + b0); v3 = softplusf(v3 + b1);
            } else if (EPI == 2) {
                const float* x0 = X + (size_t)r0 * ldc + cc;
                const float* x1 = X + (size_t)r1 * ldc + cc;
                v0 = mf0 * (x0[0] + v0); v1 = mf0 * (x0[1] + v1);
                v2 = mf1 * (x1[0] + v2); v3 = mf1 * (x1[1] + v3);
            }
            if (EPI != 3 || cc + 1 < Ntot) {
                *(float2*)(C + (size_t)r0 * ldc + cc) = make_float2(v0, v1);
                *(float2*)(C + (size_t)r1 * ldc + cc) = make_float2(v2, v3);
            }
            if (EPI == 3) {
#pragma unroll
                for (int j = 0; j < 2; j++) {
                    const int col = cc + j;
                    if (col < DTPADK) {
                        const float a0 = (col < DTRANK) ? ((j == 0) ? v0 : v1) : 0.f;
                        const float a1 = (col < DTRANK) ? ((j == 0) ? v2 : v3) : 0.f;
                        aux[(size_t)r0 * DTPADK + col] = __float2half_rn(a0);
                        aux[(size_t)r1 * DTPADK + col] = __float2half_rn(a1);
                    }
                }
            }
        }
    }
}

// --------------------------- LayerNorm + fp16 pack -------------------------
__global__ void ln_kernel(const float* __restrict__ x,
                          const int*   __restrict__ mask,
                          const float* __restrict__ g,
                          const float* __restrict__ b,
                          __half* __restrict__ xh)
{
    const int row = blockIdx.x;
    const int t   = threadIdx.x;
    const float* xr = x + (size_t)row * DIMM;

    float v[3];
    float s = 0.f, s2 = 0.f;
#pragma unroll
    for (int j = 0; j < 3; j++) {
        v[j] = xr[t + j * 256];
        s  += v[j];
        s2 += v[j] * v[j];
    }
    __shared__ float red[2][8];
#pragma unroll
    for (int o = 16; o > 0; o >>= 1) {
        s  += __shfl_xor_sync(0xffffffffu, s,  o);
        s2 += __shfl_xor_sync(0xffffffffu, s2, o);
    }
    if ((t & 31) == 0) { red[0][t >> 5] = s; red[1][t >> 5] = s2; }
    __syncthreads();
    float ts = 0.f, ts2 = 0.f;
#pragma unroll
    for (int j = 0; j < 8; j++) { ts += red[0][j]; ts2 += red[1][j]; }

    const float mu   = ts * (1.0f / DIMM);
    const float var  = ts2 * (1.0f / DIMM) - mu * mu;
    const float rstd = rsqrtf(var + 1e-5f);
    const float mf   = (float)mask[row];

#pragma unroll
    for (int j = 0; j < 3; j++) {
        const int c = t + j * 256;
        const float o = ((v[j] - mu) * rstd * g[c] + b[c]) * mf;
        xh[(size_t)row * DIMM + c] = __float2half_rn(o);
    }
}

// --------------- depthwise causal conv4 + SiLU + fp16 pack -----------------
__global__ void conv_silu(const float* __restrict__ xz,
                          const float* __restrict__ w,
                          const float* __restrict__ bias,
                          float* __restrict__ xc,
                          __half* __restrict__ xch)
{
    const long long idx = (long long)blockIdx.x * blockDim.x + threadIdx.x;
    if (idx >= (long long)NROWS * DIN) return;
    const int d = (int)(idx % DIN);
    const int i = (int)(idx / DIN);
    const int l = i % LL;

    float s = bias[d];
    const float* wp = w + d * 4;
#pragma unroll
    for (int j = 0; j < 4; j++) {
        const int ll = l - 3 + j;
        if (ll >= 0)
            s = fmaf(wp[j], xz[(size_t)(i - 3 + j) * (2 * DIN) + d], s);
    }
    const float sig = 1.f / (1.f + __expf(-s));
    const float o = s * sig;
    xc[idx] = o;
    xch[idx] = __float2half_rn(o);
}

// ======================= segmented selective scan ==========================
#define SSTAGE 8
#define STAGEF 416   // 128 dt + 128 xc + 128 z + 32 bc

template<int PHASE>
__global__ __launch_bounds__(128)
void scan_seg(const float* __restrict__ dt,
              const float* __restrict__ xc,
              const float* __restrict__ xz,
              const float* __restrict__ xdbl,
              const float* __restrict__ A_log,
              const float* __restrict__ Dp,
              float* __restrict__ Hseg,
              float* __restrict__ Eseg,
              const float* __restrict__ H0,
              __half* __restrict__ yh)
{
    __shared__ float sbuf[SSTAGE][STAGEF];

    const int bx    = blockIdx.x;
    const int b     = bx / ((DIN / 128) * NSEG);
    const int rem   = bx % ((DIN / 128) * NSEG);
    const int chunk = rem / NSEG;
    const int seg   = rem % NSEG;
    const int t     = threadIdx.x;
    const int d     = chunk * 128 + t;
    const size_t rowbase = (size_t)b * LL + (size_t)seg * SEGL;

    float a[DSTATE];
#pragma unroll
    for (int s = 0; s < DSTATE; s++) a[s] = -__expf(A_log[d * DSTATE + s]);

    bool fast = true;
#pragma unroll
    for (int s = 1; s < DSTATE; s++) {
        const float ideal = a[0] * (float)(s + 1);
        if (fabsf(a[s] - ideal) > 1e-4f * fabsf(ideal)) fast = false;
    }
    fast = __syncthreads_and(fast ? 1 : 0);

    const float LOG2E = 1.44269504088896f;
    const float c1 = a[0] * LOG2E;
    float cs[DSTATE];
#pragma unroll
    for (int s = 0; s < DSTATE; s++) cs[s] = a[s] * LOG2E;
    const float dpv = (PHASE == 1) ? Dp[d] : 0.f;

    float h[DSTATE];
    float Ecum[DSTATE];
    const size_t stOff = ((size_t)(b * NSEG + seg) * DSTATE) * DIN + d;
    if (PHASE == 0) {
#pragma unroll
        for (int s = 0; s < DSTATE; s++) { h[s] = 0.f; Ecum[s] = 1.f; }
    } else {
#pragma unroll
        for (int s = 0; s < DSTATE; s++) h[s] = H0[stOff + (size_t)s * DIN];
    }

    const int role = t >> 5;
    const int lane = t & 31;

    auto issue = [&](int tt) {
        const int slot = tt & (SSTAGE - 1);
        const size_t row = rowbase + tt;
        const float* gp = nullptr;
        int soff = 0;
        bool active = true;
        if (role == 0)      { gp = dt + row * DIN + chunk * 128 + lane * 4;             soff = lane * 4; }
        else if (role == 1) { gp = xc + row * DIN + chunk * 128 + lane * 4;             soff = 128 + lane * 4; }
        else if (role == 2) { active = (PHASE == 1);
                              gp = xz + row * (2 * DIN) + DIN + chunk * 128 + lane * 4; soff = 256 + lane * 4; }
        else                { active = (lane < 8);
                              gp = xdbl + row * XPROJ + DTRANK + lane * 4;              soff = 384 + lane * 4; }
        if (active)
            cp16((uint32_t)__cvta_generic_to_shared(&sbuf[slot][soff]), gp);
        cp_commit();
    };

    for (int tt = 0; tt < SSTAGE - 1; tt++) issue(tt);

    auto run = [&](auto fastc) {
        constexpr bool FAST = decltype(fastc)::value;
        for (int tt = 0; tt < SEGL; tt++) {
            CP_WAIT(SSTAGE - 2);
            __syncthreads();
            if (tt + SSTAGE - 1 < SEGL) issue(tt + SSTAGE - 1);

            const int slot = tt & (SSTAGE - 1);
            const float u  = sbuf[slot][t];
            const float xv = sbuf[slot][128 + t];
            float Bv[DSTATE], Cv[DSTATE];
#pragma unroll
            for (int q = 0; q < 4; q++) {
                float4 vb = *(const float4*)&sbuf[slot][384 + q * 4];
                Bv[q*4+0] = vb.x; Bv[q*4+1] = vb.y; Bv[q*4+2] = vb.z; Bv[q*4+3] = vb.w;
                if (PHASE == 1) {
                    float4 vc = *(const float4*)&sbuf[slot][400 + q * 4];
                    Cv[q*4+0] = vc.x; Cv[q*4+1] = vc.y; Cv[q*4+2] = vc.z; Cv[q*4+3] = vc.w;
                }
            }

            float e[DSTATE];
            if (FAST) {
                const float r = exp2f(u * c1);
                e[0]  = r;
                e[1]  = r * r;
                e[3]  = e[1] * e[1];
                e[7]  = e[3] * e[3];
                e[15] = e[7] * e[7];
                e[2]  = e[1] * r;
                e[4]  = e[3] * r;     e[5]  = e[3] * e[1];  e[6]  = e[3] * e[2];
                e[8]  = e[7] * r;     e[9]  = e[7] * e[1];  e[10] = e[7] * e[2];
                e[11] = e[7] * e[3];  e[12] = e[7] * e[4];  e[13] = e[7] * e[5];
                e[14] = e[7] * e[6];
            } else {
#pragma unroll
                for (int s = 0; s < DSTATE; s++) e[s] = exp2f(u * cs[s]);
            }

            const float ux = u * xv;
            if (PHASE == 0) {
#pragma unroll
                for (int s = 0; s < DSTATE; s++) {
                    h[s]    = fmaf(e[s], h[s], ux * Bv[s]);
                    Ecum[s] = Ecum[s] * e[s];
                }
            } else {
                const float zv = sbuf[slot][256 + t];
                float y0 = 0.f, y1 = 0.f, y2 = 0.f, y3 = 0.f;
#pragma unroll
                for (int s = 0; s < DSTATE; s += 4) {
                    h[s+0] = fmaf(e[s+0], h[s+0], ux * Bv[s+0]);
                    h[s+1] = fmaf(e[s+1], h[s+1], ux * Bv[s+1]);
                    h[s+2] = fmaf(e[s+2], h[s+2], ux * Bv[s+2]);
                    h[s+3] = fmaf(e[s+3], h[s+3], ux * Bv[s+3]);
                    y0 = fmaf(h[s+0], Cv[s+0], y0);
                    y1 = fmaf(h[s+1], Cv[s+1], y1);
                    y2 = fmaf(h[s+2], Cv[s+2], y2);
                    y3 = fmaf(h[s+3], Cv[s+3], y3);
                }
                float yt = (y0 + y1) + (y2 + y3);
                yt = fmaf(xv, dpv, yt);
                const float sig = 1.f / (1.f + __expf(-zv));
                const float out = yt * (zv * sig);
                yh[(rowbase + tt) * DIN + chunk * 128 + t] = __float2half_rn(out);
            }
        }
    };

    if (fast) run(std::true_type{});
    else      run(std::false_type{});

    if (PHASE == 0) {
#pragma unroll
        for (int s = 0; s < DSTATE; s++) {
            Hseg[stOff + (size_t)s * DIN] = h[s];
            Eseg[stOff + (size_t)s * DIN] = Ecum[s];
        }
    }
}

// sequential composition across segments: H0[b][seg] = state entering segment
__global__ void scan_combine(const float* __restrict__ Hseg,
                             const float* __restrict__ Eseg,
                             float* __restrict__ H0)
{
    const int idx = blockIdx.x * blockDim.x + threadIdx.x;
    if (idx >= BB * DIN) return;
    const int b = idx / DIN, d = idx % DIN;
    float h[DSTATE];
#pragma unroll
    for (int s = 0; s < DSTATE; s++) h[s] = 0.f;
    for (int seg = 0; seg < NSEG; seg++) {
        const size_t o = ((size_t)(b * NSEG + seg) * DSTATE) * DIN + d;
#pragma unroll
        for (int s = 0; s < DSTATE; s++) {
            const size_t os = o + (size_t)s * DIN;
            H0[os] = h[s];
            h[s] = fmaf(Eseg[os], h[s], Hseg[os]);
        }
    }
}

// ------------------------------------------------------------------- launch
extern "C" void kernel_launch(void* const* d_in, const int* in_sizes, int n_in,
                              void* d_out, int out_size)
{
    const float* x      = (const float*)d_in[0];
    const int*   mask   = (const int*)  d_in[1];
    const float* ln_g   = (const float*)d_in[2];
    const float* ln_b   = (const float*)d_in[3];
    const float* W_in   = (const float*)d_in[4];
    const float* conv_w = (const float*)d_in[5];
    const float* conv_b = (const float*)d_in[6];
    const float* W_xp   = (const float*)d_in[7];
    const float* W_dt   = (const float*)d_in[8];
    const float* b_dt   = (const float*)d_in[9];
    const float* A_log  = (const float*)d_in[10];
    const float* Dp     = (const float*)d_in[11];
    const float* W_out  = (const float*)d_in[12];
    float* out = (float*)d_out;

    static float *p_xz = nullptr, *p_xc, *p_xdbl, *p_dt, *p_Hs, *p_Es, *p_H0;
    static __half *p_ax, *p_wi, *p_ay, *p_wo, *p_xc16, *p_wx, *p_xd, *p_wd;
    if (!p_xz) {
        cudaGetSymbolAddress((void**)&p_xz,   g_xz);
        cudaGetSymbolAddress((void**)&p_xc,   g_xc);
        cudaGetSymbolAddress((void**)&p_xdbl, g_xdbl);
        cudaGetSymbolAddress((void**)&p_dt,   g_dt);
        cudaGetSymbolAddress((void**)&p_Hs,   g_Hseg);
        cudaGetSymbolAddress((void**)&p_Es,   g_Eseg);
        cudaGetSymbolAddress((void**)&p_H0,   g_H0);
        cudaGetSymbolAddress((void**)&p_ax,   g_ax);
        cudaGetSymbolAddress((void**)&p_wi,   g_wi);
        cudaGetSymbolAddress((void**)&p_ay,   g_ay);
        cudaGetSymbolAddress((void**)&p_wo,   g_wo);
        cudaGetSymbolAddress((void**)&p_xc16, g_xc16);
        cudaGetSymbolAddress((void**)&p_wx,   g_wx);
        cudaGetSymbolAddress((void**)&p_xd,   g_xd);
        cudaGetSymbolAddress((void**)&p_wd,   g_wd);
        cudaFuncSetAttribute(tgemm<0>, cudaFuncAttributeMaxDynamicSharedMemorySize, MM_SMEM);
        cudaFuncSetAttribute(tgemm<1>, cudaFuncAttributeMaxDynamicSharedMemorySize, MM_SMEM);
        cudaFuncSetAttribute(tgemm<2>, cudaFuncAttributeMaxDynamicSharedMemorySize, MM_SMEM);
        cudaFuncSetAttribute(tgemm<3>, cudaFuncAttributeMaxDynamicSharedMemorySize, MM_SMEM);
    }

    // 1. LayerNorm + mask + fp16 pack
    ln_kernel<<<NROWS, 256>>>(x, mask, ln_g, ln_b, p_ax);

    // 2. pack weights
    {
        long long nW = (long long)(2 * DIN) * DIMM / 8;
        pack_h<<<(unsigned)((nW + 255) / 256), 256>>>(W_in, (uint4*)p_wi, nW);
        long long nO = (long long)DIMM * DIN / 8;
        pack_h<<<(unsigned)((nO + 255) / 256), 256>>>(W_out, (uint4*)p_wo, nO);
        pack_pad<<<(128 * DIN + 255) / 256, 256>>>(W_xp, p_wx, XPROJ, DIN, 128, DIN);
        pack_pad<<<(DIN * DTPADK + 255) / 256, 256>>>(W_dt, p_wd, DIN, DTRANK, DIN, DTPADK);
    }

    // 3. in_proj: xz = xn @ W_in^T   (16384 x 3072, K=768)
    {
        dim3 g((2 * DIN) / 128, NROWS / 128);
        tgemm<0><<<g, 256, MM_SMEM>>>(p_ax, p_wi, p_xz, 2 * DIN, DIMM, 2 * DIN,
                                      nullptr, nullptr, nullptr, nullptr);
    }

    // 4. depthwise causal conv + SiLU (+ fp16 pack of xc)
    {
        const long long n = (long long)NROWS * DIN;
        conv_silu<<<(unsigned)((n + 255) / 256), 256>>>(p_xz, conv_w, conv_b,
                                                        p_xc, p_xc16);
    }

    // 5. x_proj on tensor: xdbl = xc @ W_xp^T (N pad 80->128, K=1536)
    {
        dim3 g(1, NROWS / 128);
        tgemm<3><<<g, 256, MM_SMEM>>>(p_xc16, p_wx, p_xdbl, XPROJ, DIN, XPROJ,
                                      nullptr, nullptr, nullptr, p_xd);
    }

    // 6. dt_proj on tensor + softplus (K padded 48->64)
    {
        dim3 g(DIN / 128, NROWS / 128);
        tgemm<1><<<g, 256, MM_SMEM>>>(p_xd, p_wd, p_dt, DIN, DTPADK, DIN,
                                      b_dt, nullptr, nullptr, nullptr);
    }

    // 7. segmented selective scan (A: local states, B: compose, C: emit y)
    {
        const int nblk = BB * (DIN / 128) * NSEG;   // 768
        scan_seg<0><<<nblk, 128>>>(p_dt, p_xc, p_xz, p_xdbl, A_log, Dp,
                                   p_Hs, p_Es, nullptr, nullptr);
        scan_combine<<<(BB * DIN + 255) / 256, 256>>>(p_Hs, p_Es, p_H0);
        scan_seg<1><<<nblk, 128>>>(p_dt, p_xc, p_xz, p_xdbl, A_log, Dp,
                                   nullptr, nullptr, p_H0, p_ay);
    }

    // 8. out_proj + residual + mask
    {
        dim3 g(DIMM / 128, NROWS / 128);
        tgemm<2><<<g, 256, MM_SMEM>>>(p_ay, p_wo, out, DIMM, DIN, DIMM,
                                      nullptr, x, mask, nullptr);
    }
}